// round 1
// baseline (speedup 1.0000x reference)
#include <cuda_runtime.h>

#define NB 2
#define NC 512
#define NH 32
#define NW 32
#define HW 1024
#define NG 8
#define DH 64
#define BG 16      // NB*NG
#define JD 64      // Hd*Wd = 8*8
#define EPSBN 1e-5f

// ---------------- scratch (static device globals; no allocation) ----------------
__device__ float g_xn[NB*NC*HW];     // 4 MB  bn1(x)
__device__ float g_q[NB*NC*HW];      // 4 MB  q projection
__device__ float g_grid[BG*JD*2];    // sampled grid (nx,ny)
__device__ float g_k[BG*DH*JD];      // k  [bg][d][j]
__device__ float g_v[BG*DH*JD];      // v  [bg][d][j]
__device__ float g_bias[BG*HW*JD];   // 4 MB CPB bias [bg][i][j]
__device__ float g_attn[NB*NC*HW];   // 4 MB attention output (pre-proj)
__device__ float g_x2[NB*NC*HW];     // 4 MB after first residual
__device__ float g_xn2[NB*NC*HW];    // 4 MB bn2(x2)
__device__ float g_h1[NB*2048*HW];   // 16 MB MLP hidden

__device__ __forceinline__ float gelu_exact(float x){
    return 0.5f*x*(1.0f+erff(x*0.7071067811865476f));
}

// ---------------- 1) bn1 ----------------
__global__ void k_bn1(const float* __restrict__ x, const float* __restrict__ g1,
                      const float* __restrict__ b1){
    int idx = blockIdx.x*256 + threadIdx.x;           // 2*512*1024 = 1048576
    int c = (idx>>10)&(NC-1);
    float s = g1[c]*rsqrtf(1.0f+EPSBN);
    g_xn[idx] = x[idx]*s + b1[c];
}

// ---------------- 2) q grouped 1x1 conv ----------------
__global__ void k_qproj(const float* __restrict__ qw){
    __shared__ float ws[DH*DH];     // [o][c]
    __shared__ float xs[DH*128];    // [c][col]
    int bg = blockIdx.y; int b = bg>>3, g = bg&7;
    int p0 = blockIdx.x*128;
    int tid = threadIdx.x;          // 128
    const float* wsrc = qw + g*DH*DH;
    for(int i=tid;i<DH*DH;i+=128) ws[i]=wsrc[i];
    const float* xsrc = g_xn + (b*NC + g*DH)*HW + p0;
    for(int i=tid;i<DH*128;i+=128){ int c=i>>7, col=i&127; xs[c*128+col]=xsrc[c*HW+col]; }
    __syncthreads();
    float acc[DH];
    #pragma unroll
    for(int o=0;o<DH;o++) acc[o]=0.f;
    for(int c=0;c<DH;c++){
        float xv = xs[c*128+tid];
        #pragma unroll
        for(int o=0;o<DH;o++) acc[o] += ws[o*DH+c]*xv;
    }
    float* qdst = g_q + (b*NC + g*DH)*HW + p0 + tid;
    #pragma unroll
    for(int o=0;o<DH;o++) qdst[o*HW]=acc[o];
}

// ---------------- 3) offsets: dwconv6x6 s4 p1 -> gelu -> 1x1 -> tanh*4 -> grid ----------------
__global__ void k_offsets(const float* __restrict__ dw, const float* __restrict__ dwb,
                          const float* __restrict__ pw){
    __shared__ float dws[DH*36];
    int bg = blockIdx.x; int tid = threadIdx.x;       // 64 threads = 8x8 out positions
    for(int i=tid;i<DH*36;i+=64) dws[i]=dw[i];
    __syncthreads();
    int b=bg>>3, g=bg&7;
    int oy=tid>>3, ox=tid&7;
    const float* qp = g_q + (b*NC+g*DH)*HW;
    float a0=0.f, a1=0.f;
    for(int ch=0;ch<DH;ch++){
        const float* qc = qp + ch*HW;
        float s=0.f;
        #pragma unroll
        for(int ky=0;ky<6;ky++){
            int iy = oy*4-1+ky;
            if(iy<0||iy>=NH) continue;
            #pragma unroll
            for(int kx=0;kx<6;kx++){
                int ix = ox*4-1+kx;
                if(ix<0||ix>=NW) continue;
                s += qc[iy*NW+ix]*dws[ch*36+ky*6+kx];
            }
        }
        s = gelu_exact(s + dwb[ch]);
        a0 += s*pw[ch];
        a1 += s*pw[DH+ch];
    }
    float t0 = tanhf(a0)*4.0f;
    float t1 = tanhf(a1)*4.0f;
    float vx = (float)ox + t0;
    float vy = (float)oy + t1;
    g_grid[(bg*JD+tid)*2+0] = 2.0f*vx/7.0f - 1.0f;
    g_grid[(bg*JD+tid)*2+1] = 2.0f*vy/7.0f - 1.0f;
}

// ---------------- 4) grid_sample + k/v grouped conv ----------------
__global__ void k_sample(const float* __restrict__ kw, const float* __restrict__ vw){
    __shared__ float kvs[DH*JD];
    __shared__ float kws[DH*DH];
    __shared__ float vws[DH*DH];
    int bg=blockIdx.x, tid=threadIdx.x;               // 256 threads
    int b=bg>>3, g=bg&7;
    for(int i=tid;i<DH*DH;i+=256){ kws[i]=kw[g*DH*DH+i]; vws[i]=vw[g*DH*DH+i]; }
    const float* img = g_xn + (b*NC+g*DH)*HW;
    for(int i=tid;i<DH*JD;i+=256){
        int c=i>>6, j=i&63;
        float nx=g_grid[(bg*JD+j)*2], ny=g_grid[(bg*JD+j)*2+1];
        float gx=(nx+1.0f)*16.0f-0.5f;
        float gy=(ny+1.0f)*16.0f-0.5f;
        float x0f=floorf(gx), y0f=floorf(gy);
        float wx=gx-x0f, wy=gy-y0f;
        int x0=(int)x0f, y0=(int)y0f;
        const float* im=img+c*HW;
        float v00=0.f,v01=0.f,v10=0.f,v11=0.f;
        bool xi0 = (x0>=0)&&(x0<NW), xi1 = (x0+1>=0)&&(x0+1<NW);
        bool yi0 = (y0>=0)&&(y0<NH), yi1 = (y0+1>=0)&&(y0+1<NH);
        if(yi0){ if(xi0) v00=im[y0*NW+x0]; if(xi1) v01=im[y0*NW+x0+1]; }
        if(yi1){ if(xi0) v10=im[(y0+1)*NW+x0]; if(xi1) v11=im[(y0+1)*NW+x0+1]; }
        kvs[c*JD+j] = v00*(1.f-wx)*(1.f-wy)+v01*wx*(1.f-wy)+v10*(1.f-wx)*wy+v11*wx*wy;
    }
    __syncthreads();
    for(int i=tid;i<DH*JD;i+=256){
        int o=i>>6, j=i&63;
        float ka=0.f,va=0.f;
        for(int c=0;c<DH;c++){
            float kvv=kvs[c*JD+j];
            ka += kws[o*DH+c]*kvv;
            va += vws[o*DH+c]*kvv;
        }
        g_k[bg*DH*JD + i] = ka;
        g_v[bg*DH*JD + i] = va;
    }
}

// ---------------- 5) CPB bias MLP (the heavy one) ----------------
// per block: 128 points (2 i's x 64 j's). Fuses layer1 (build h1 into smem A tile),
// layer2 (128x128x128 GEMM, 8x8 reg tile), layer3 (dot w3 in epilogue + reduction).
__global__ void k_cpb(const float* __restrict__ w1, const float* __restrict__ b1,
                      const float* __restrict__ w2, const float* __restrict__ b2,
                      const float* __restrict__ w3, const float* __restrict__ b3){
    extern __shared__ float sm[];
    float* Hs  = sm;                 // 128*132  h1, k-major [k][pt]
    float* Ws  = Hs + 128*132;       // 128*132  w2 [k][n]
    float* red = Ws + 128*132;       // 16*129
    float* f0s = red + 16*129;       // 128
    float* f1s = f0s + 128;
    float* b2s = f1s + 128;
    float* w3s = b2s + 128;
    int tid = threadIdx.x;           // 256
    int pt0 = blockIdx.x*128;        // 8192 blocks
    int bg  = pt0>>16;
    if(tid<128){
        int pt = pt0 + tid;
        int i = (pt>>6)&1023;
        int j = pt&63;
        float qx = 2.0f*(float)(i&31)*(1.0f/31.0f) - 1.0f;
        float qy = 2.0f*(float)(i>>5)*(1.0f/31.0f) - 1.0f;
        float kx = g_grid[(bg*JD+j)*2];
        float ky = g_grid[(bg*JD+j)*2+1];
        float p0 = qx-kx, p1 = qy-ky;
        f0s[tid] = copysignf(log1pf(fabsf(p0)), p0);
        f1s[tid] = copysignf(log1pf(fabsf(p1)), p1);
        b2s[tid] = b2[tid];
        w3s[tid] = w3[tid];
    }
    for(int i4=tid;i4<128*32;i4+=256){                // w2 -> smem (vectorized)
        int k=i4>>5, nq=i4&31;
        float4 vv = *(const float4*)(w2 + k*128 + nq*4);
        *(float4*)(Ws + k*132 + nq*4) = vv;
    }
    __syncthreads();
    for(int idx=tid;idx<128*128;idx+=256){            // layer1 -> Hs
        int k=idx>>7, pt=idx&127;
        float h = f0s[pt]*w1[k] + f1s[pt]*w1[128+k] + b1[k];
        Hs[k*132+pt] = fmaxf(h,0.f);
    }
    __syncthreads();
    int ty=tid>>4, tx=tid&15;
    float acc[8][8];
    #pragma unroll
    for(int i=0;i<8;i++){
        #pragma unroll
        for(int j=0;j<8;j++) acc[i][j]=0.f;
    }
    const float* hb = Hs + ty*8;
    const float* wb = Ws + tx*8;
    #pragma unroll 4
    for(int k=0;k<128;k++){
        float4 a0 = *(const float4*)(hb + k*132);
        float4 a1 = *(const float4*)(hb + k*132 + 4);
        float4 c0 = *(const float4*)(wb + k*132);
        float4 c1 = *(const float4*)(wb + k*132 + 4);
        float av[8] = {a0.x,a0.y,a0.z,a0.w,a1.x,a1.y,a1.z,a1.w};
        float bv[8] = {c0.x,c0.y,c0.z,c0.w,c1.x,c1.y,c1.z,c1.w};
        #pragma unroll
        for(int i=0;i<8;i++){
            #pragma unroll
            for(int j=0;j<8;j++) acc[i][j] += av[i]*bv[j];
        }
    }
    float part[8];
    #pragma unroll
    for(int i=0;i<8;i++) part[i]=0.f;
    #pragma unroll
    for(int j=0;j<8;j++){                              // layer3 fused
        int n = tx*8+j;
        float bb = b2s[n], w3v = w3s[n];
        #pragma unroll
        for(int i=0;i<8;i++){
            float h2 = acc[i][j]+bb;
            part[i] += fmaxf(h2,0.f)*w3v;
        }
    }
    #pragma unroll
    for(int i=0;i<8;i++) red[tx*129 + ty*8 + i] = part[i];
    __syncthreads();
    if(tid<128){
        float s = b3[0];
        #pragma unroll
        for(int t=0;t<16;t++) s += red[t*129+tid];
        g_bias[pt0+tid] = s;
    }
}

// ---------------- 6) attention (j = 64 keys, per-thread softmax) ----------------
__global__ void k_attn(){
    __shared__ float ks[DH*JD];
    __shared__ float vs[DH*JD];
    int bg=blockIdx.y, it=blockIdx.x, tid=threadIdx.x;  // 128 threads
    int b=bg>>3, g=bg&7;
    for(int i=tid;i<DH*JD;i+=128){ ks[i]=g_k[bg*DH*JD+i]; vs[i]=g_v[bg*DH*JD+i]; }
    __syncthreads();
    int i = it*128 + tid;
    const float* qp = g_q + (b*NC+g*DH)*HW + i;
    float sim[JD];
    #pragma unroll
    for(int j=0;j<JD;j++) sim[j]=0.f;
    for(int d=0;d<DH;d++){
        float qv = qp[d*HW];
        #pragma unroll
        for(int j=0;j<JD;j++) sim[j] += qv*ks[d*JD+j];
    }
    const float scale = 0.125f;                        // 64^-0.5
    const float* bp = g_bias + (bg*HW + i)*JD;
    float m=-1e30f;
    #pragma unroll
    for(int j=0;j<JD;j++){ sim[j] = sim[j]*scale + bp[j]; m=fmaxf(m,sim[j]); }
    float ssum=0.f;
    #pragma unroll
    for(int j=0;j<JD;j++){ sim[j]=expf(sim[j]-m); ssum+=sim[j]; }
    float inv = 1.0f/ssum;
    float* op = g_attn + (b*NC+g*DH)*HW + i;
    for(int d=0;d<DH;d++){
        float a=0.f;
        #pragma unroll
        for(int j=0;j<JD;j++) a += sim[j]*vs[d*JD+j];
        op[d*HW] = a*inv;
    }
}

// ---------------- 7) out projection + residual + fused bn2 ----------------
__global__ void k_outproj(const float* __restrict__ ow, const float* __restrict__ ob,
                          const float* __restrict__ x, const float* __restrict__ g2,
                          const float* __restrict__ bb2){
    __shared__ float As[32*68];   // [k][m], m<64
    __shared__ float Bs[32*132];  // [k][n], n<128
    int mt = blockIdx.y, nt = blockIdx.x;
    int m0 = mt*64, n0 = nt*128;
    int b = n0>>10, p0 = n0&1023;
    int tid = threadIdx.x, ty = tid>>4, tx = tid&15;
    float acc[4][8];
    #pragma unroll
    for(int i=0;i<4;i++){
        #pragma unroll
        for(int j=0;j<8;j++) acc[i][j]=0.f;
    }
    for(int k0=0;k0<512;k0+=32){
        for(int idx=tid;idx<2048;idx+=256){
            int k=idx&31, m=idx>>5;
            As[k*68+m] = ow[(m0+m)*512 + k0+k];
        }
        for(int idx=tid;idx<4096;idx+=256){
            int k=idx>>7, n=idx&127;
            Bs[k*132+n] = g_attn[b*NC*HW + (k0+k)*HW + p0+n];
        }
        __syncthreads();
        #pragma unroll 4
        for(int k=0;k<32;k++){
            float4 av = *(const float4*)(As + k*68 + ty*4);
            float4 c0 = *(const float4*)(Bs + k*132 + tx*8);
            float4 c1 = *(const float4*)(Bs + k*132 + tx*8 + 4);
            float a[4]={av.x,av.y,av.z,av.w};
            float bv[8]={c0.x,c0.y,c0.z,c0.w,c1.x,c1.y,c1.z,c1.w};
            #pragma unroll
            for(int i=0;i<4;i++){
                #pragma unroll
                for(int j=0;j<8;j++) acc[i][j]+=a[i]*bv[j];
            }
        }
        __syncthreads();
    }
    #pragma unroll
    for(int i=0;i<4;i++){
        int m = m0 + ty*4 + i;
        float bias = ob[m];
        float s2 = g2[m]*rsqrtf(1.0f+EPSBN);
        float bb = bb2[m];
        #pragma unroll
        for(int j=0;j<8;j++){
            int n = tx*8+j;
            int off = b*NC*HW + m*HW + p0+n;
            float val = x[off] + acc[i][j] + bias;
            g_x2[off]=val;
            g_xn2[off]=val*s2+bb;
        }
    }
}

// ---------------- 8) MLP conv1: 2048 <- 512, gelu ----------------
__global__ void k_mlp1(const float* __restrict__ w, const float* __restrict__ bias){
    __shared__ float As[32*132];
    __shared__ float Bs[32*132];
    int mt=blockIdx.y, nt=blockIdx.x;
    int m0=mt*128, n0=nt*128;
    int b=n0>>10, p0=n0&1023;
    int tid=threadIdx.x, ty=tid>>4, tx=tid&15;
    float acc[8][8];
    #pragma unroll
    for(int i=0;i<8;i++){
        #pragma unroll
        for(int j=0;j<8;j++) acc[i][j]=0.f;
    }
    for(int k0=0;k0<512;k0+=32){
        for(int idx=tid;idx<4096;idx+=256){
            int k=idx&31, m=idx>>5;
            As[k*132+m] = w[(m0+m)*512+k0+k];
        }
        for(int idx=tid;idx<4096;idx+=256){
            int k=idx>>7, n=idx&127;
            Bs[k*132+n] = g_xn2[b*NC*HW + (k0+k)*HW + p0+n];
        }
        __syncthreads();
        #pragma unroll 2
        for(int k=0;k<32;k++){
            float4 a0=*(const float4*)(As+k*132+ty*8);
            float4 a1=*(const float4*)(As+k*132+ty*8+4);
            float4 c0=*(const float4*)(Bs+k*132+tx*8);
            float4 c1=*(const float4*)(Bs+k*132+tx*8+4);
            float a[8]={a0.x,a0.y,a0.z,a0.w,a1.x,a1.y,a1.z,a1.w};
            float bv[8]={c0.x,c0.y,c0.z,c0.w,c1.x,c1.y,c1.z,c1.w};
            #pragma unroll
            for(int i=0;i<8;i++){
                #pragma unroll
                for(int j=0;j<8;j++) acc[i][j]+=a[i]*bv[j];
            }
        }
        __syncthreads();
    }
    #pragma unroll
    for(int i=0;i<8;i++){
        int m=m0+ty*8+i;
        float bi=bias[m];
        #pragma unroll
        for(int j=0;j<8;j++){
            int n=tx*8+j;
            g_h1[b*2048*HW + m*HW + p0+n] = gelu_exact(acc[i][j]+bi);
        }
    }
}

// ---------------- 9) MLP conv2: 512 <- 2048, + residual -> out ----------------
__global__ void k_mlp2(const float* __restrict__ w, const float* __restrict__ bias,
                       float* __restrict__ out){
    __shared__ float As[32*68];
    __shared__ float Bs[32*132];
    int mt=blockIdx.y, nt=blockIdx.x;
    int m0=mt*64, n0=nt*128;
    int b=n0>>10, p0=n0&1023;
    int tid=threadIdx.x, ty=tid>>4, tx=tid&15;
    float acc[4][8];
    #pragma unroll
    for(int i=0;i<4;i++){
        #pragma unroll
        for(int j=0;j<8;j++) acc[i][j]=0.f;
    }
    for(int k0=0;k0<2048;k0+=32){
        for(int idx=tid;idx<2048;idx+=256){
            int k=idx&31, m=idx>>5;
            As[k*68+m]=w[(m0+m)*2048+k0+k];
        }
        for(int idx=tid;idx<4096;idx+=256){
            int k=idx>>7, n=idx&127;
            Bs[k*132+n]=g_h1[b*2048*HW+(k0+k)*HW+p0+n];
        }
        __syncthreads();
        #pragma unroll 4
        for(int k=0;k<32;k++){
            float4 av=*(const float4*)(As+k*68+ty*4);
            float4 c0=*(const float4*)(Bs+k*132+tx*8);
            float4 c1=*(const float4*)(Bs+k*132+tx*8+4);
            float a[4]={av.x,av.y,av.z,av.w};
            float bv[8]={c0.x,c0.y,c0.z,c0.w,c1.x,c1.y,c1.z,c1.w};
            #pragma unroll
            for(int i=0;i<4;i++){
                #pragma unroll
                for(int j=0;j<8;j++) acc[i][j]+=a[i]*bv[j];
            }
        }
        __syncthreads();
    }
    #pragma unroll
    for(int i=0;i<4;i++){
        int m=m0+ty*4+i;
        float bi=bias[m];
        #pragma unroll
        for(int j=0;j<8;j++){
            int n=tx*8+j;
            int off=b*NC*HW+m*HW+p0+n;
            out[off]=g_x2[off]+acc[i][j]+bi;
        }
    }
}

// ---------------- launch ----------------
extern "C" void kernel_launch(void* const* d_in, const int* in_sizes, int n_in,
                              void* d_out, int out_size){
    const float* x    = (const float*)d_in[0];
    const float* bn1g = (const float*)d_in[1];
    const float* bn1b = (const float*)d_in[2];
    const float* bn2g = (const float*)d_in[3];
    const float* bn2b = (const float*)d_in[4];
    const float* qw   = (const float*)d_in[5];
    const float* kw   = (const float*)d_in[6];
    const float* vw   = (const float*)d_in[7];
    const float* ow   = (const float*)d_in[8];
    const float* obv  = (const float*)d_in[9];
    const float* dw   = (const float*)d_in[10];
    const float* dwb  = (const float*)d_in[11];
    const float* pw   = (const float*)d_in[12];
    const float* cw1  = (const float*)d_in[13];
    const float* cb1  = (const float*)d_in[14];
    const float* cw2  = (const float*)d_in[15];
    const float* cb2  = (const float*)d_in[16];
    const float* cw3  = (const float*)d_in[17];
    const float* cb3  = (const float*)d_in[18];
    const float* mw1  = (const float*)d_in[19];
    const float* mb1  = (const float*)d_in[20];
    const float* mw2  = (const float*)d_in[21];
    const float* mb2  = (const float*)d_in[22];
    float* out = (float*)d_out;

    static_assert(sizeof(float)==4, "");
    const int cpb_smem = (128*132*2 + 16*129 + 4*128) * 4;   // 145472 B
    cudaFuncSetAttribute(k_cpb, cudaFuncAttributeMaxDynamicSharedMemorySize, cpb_smem);

    k_bn1    <<<4096,256>>>(x,bn1g,bn1b);
    k_qproj  <<<dim3(8,16),128>>>(qw);
    k_offsets<<<16,64>>>(dw,dwb,pw);
    k_sample <<<16,256>>>(kw,vw);
    k_cpb    <<<8192,256,cpb_smem>>>(cw1,cb1,cw2,cb2,cw3,cb3);
    k_attn   <<<dim3(8,16),128>>>();
    k_outproj<<<dim3(16,8),256>>>(ow,obv,x,bn2g,bn2b);
    k_mlp1   <<<dim3(16,16),256>>>(mw1,mb1);
    k_mlp2   <<<dim3(16,8),256>>>(mw2,mb2,out);
}

// round 2
// speedup vs baseline: 1.5967x; 1.5967x over previous
#include <cuda_runtime.h>
#include <cstdint>

#define NB 2
#define NC 512
#define NH 32
#define NW 32
#define HW 1024
#define NG 8
#define DH 64
#define BG 16      // NB*NG
#define JD 64      // Hd*Wd = 8*8
#define EPSBN 1e-5f

// ---------------- scratch (static device globals; no allocation) ----------------
__device__ float g_xn[NB*NC*HW];     // 4 MB  bn1(x)
__device__ float g_q[NB*NC*HW];      // 4 MB  q projection
__device__ float g_grid[BG*JD*2];    // sampled grid (nx,ny)
__device__ float g_k[BG*DH*JD];      // k  [bg][d][j]
__device__ float g_v[BG*DH*JD];      // v  [bg][d][j]
__device__ float g_bias[BG*HW*JD];   // 4 MB CPB bias [bg][i][j]
__device__ float g_attn[NB*NC*HW];   // 4 MB attention output (pre-proj)
__device__ float g_x2[NB*NC*HW];     // 4 MB after first residual
__device__ float g_xn2[NB*NC*HW];    // 4 MB bn2(x2)
__device__ float g_h1[NB*2048*HW];   // 16 MB MLP hidden

__device__ __forceinline__ float gelu_exact(float x){
    return 0.5f*x*(1.0f+erff(x*0.7071067811865476f));
}
__device__ __forceinline__ uint32_t f2tf(float v){
    uint32_t r; asm("cvt.rna.tf32.f32 %0, %1;" : "=r"(r) : "f"(v)); return r;
}
__device__ __forceinline__ void mma_tf32(float c[4], const uint32_t a[4], const uint32_t b[2]){
    asm volatile("mma.sync.aligned.m16n8k8.row.col.f32.tf32.tf32.f32 "
        "{%0,%1,%2,%3}, {%4,%5,%6,%7}, {%8,%9}, {%0,%1,%2,%3};"
        : "+f"(c[0]),"+f"(c[1]),"+f"(c[2]),"+f"(c[3])
        : "r"(a[0]),"r"(a[1]),"r"(a[2]),"r"(a[3]),"r"(b[0]),"r"(b[1]));
}

// ---------------- 1) bn1 ----------------
__global__ void k_bn1(const float* __restrict__ x, const float* __restrict__ g1,
                      const float* __restrict__ b1){
    int idx = blockIdx.x*256 + threadIdx.x;
    int c = (idx>>10)&(NC-1);
    float s = g1[c]*rsqrtf(1.0f+EPSBN);
    g_xn[idx] = x[idx]*s + b1[c];
}

// ---------------- 2) q grouped 1x1 conv ----------------
__global__ void k_qproj(const float* __restrict__ qw){
    __shared__ float ws[DH*DH];
    __shared__ float xs[DH*128];
    int bg = blockIdx.y; int b = bg>>3, g = bg&7;
    int p0 = blockIdx.x*128;
    int tid = threadIdx.x;
    const float* wsrc = qw + g*DH*DH;
    for(int i=tid;i<DH*DH;i+=128) ws[i]=wsrc[i];
    const float* xsrc = g_xn + (b*NC + g*DH)*HW + p0;
    for(int i=tid;i<DH*128;i+=128){ int c=i>>7, col=i&127; xs[c*128+col]=xsrc[c*HW+col]; }
    __syncthreads();
    float acc[DH];
    #pragma unroll
    for(int o=0;o<DH;o++) acc[o]=0.f;
    for(int c=0;c<DH;c++){
        float xv = xs[c*128+tid];
        #pragma unroll
        for(int o=0;o<DH;o++) acc[o] += ws[o*DH+c]*xv;
    }
    float* qdst = g_q + (b*NC + g*DH)*HW + p0 + tid;
    #pragma unroll
    for(int o=0;o<DH;o++) qdst[o*HW]=acc[o];
}

// ---------------- 3) offsets ----------------
__global__ void k_offsets(const float* __restrict__ dw, const float* __restrict__ dwb,
                          const float* __restrict__ pw){
    __shared__ float dws[DH*36];
    int bg = blockIdx.x; int tid = threadIdx.x;
    for(int i=tid;i<DH*36;i+=64) dws[i]=dw[i];
    __syncthreads();
    int b=bg>>3, g=bg&7;
    int oy=tid>>3, ox=tid&7;
    const float* qp = g_q + (b*NC+g*DH)*HW;
    float a0=0.f, a1=0.f;
    for(int ch=0;ch<DH;ch++){
        const float* qc = qp + ch*HW;
        float s=0.f;
        #pragma unroll
        for(int ky=0;ky<6;ky++){
            int iy = oy*4-1+ky;
            if(iy<0||iy>=NH) continue;
            #pragma unroll
            for(int kx=0;kx<6;kx++){
                int ix = ox*4-1+kx;
                if(ix<0||ix>=NW) continue;
                s += qc[iy*NW+ix]*dws[ch*36+ky*6+kx];
            }
        }
        s = gelu_exact(s + dwb[ch]);
        a0 += s*pw[ch];
        a1 += s*pw[DH+ch];
    }
    float vx = (float)ox + tanhf(a0)*4.0f;
    float vy = (float)oy + tanhf(a1)*4.0f;
    g_grid[(bg*JD+tid)*2+0] = 2.0f*vx/7.0f - 1.0f;
    g_grid[(bg*JD+tid)*2+1] = 2.0f*vy/7.0f - 1.0f;
}

// ---------------- 4) grid_sample + k/v grouped conv ----------------
__global__ void k_sample(const float* __restrict__ kw, const float* __restrict__ vw){
    __shared__ float kvs[DH*JD];
    __shared__ float kws[DH*DH];
    __shared__ float vws[DH*DH];
    int bg=blockIdx.x, tid=threadIdx.x;
    int b=bg>>3, g=bg&7;
    for(int i=tid;i<DH*DH;i+=256){ kws[i]=kw[g*DH*DH+i]; vws[i]=vw[g*DH*DH+i]; }
    const float* img = g_xn + (b*NC+g*DH)*HW;
    for(int i=tid;i<DH*JD;i+=256){
        int c=i>>6, j=i&63;
        float nx=g_grid[(bg*JD+j)*2], ny=g_grid[(bg*JD+j)*2+1];
        float gx=(nx+1.0f)*16.0f-0.5f;
        float gy=(ny+1.0f)*16.0f-0.5f;
        float x0f=floorf(gx), y0f=floorf(gy);
        float wx=gx-x0f, wy=gy-y0f;
        int x0=(int)x0f, y0=(int)y0f;
        const float* im=img+c*HW;
        float v00=0.f,v01=0.f,v10=0.f,v11=0.f;
        bool xi0 = (x0>=0)&&(x0<NW), xi1 = (x0+1>=0)&&(x0+1<NW);
        bool yi0 = (y0>=0)&&(y0<NH), yi1 = (y0+1>=0)&&(y0+1<NH);
        if(yi0){ if(xi0) v00=im[y0*NW+x0]; if(xi1) v01=im[y0*NW+x0+1]; }
        if(yi1){ if(xi0) v10=im[(y0+1)*NW+x0]; if(xi1) v11=im[(y0+1)*NW+x0+1]; }
        kvs[c*JD+j] = v00*(1.f-wx)*(1.f-wy)+v01*wx*(1.f-wy)+v10*(1.f-wx)*wy+v11*wx*wy;
    }
    __syncthreads();
    for(int i=tid;i<DH*JD;i+=256){
        int o=i>>6, j=i&63;
        float ka=0.f,va=0.f;
        for(int c=0;c<DH;c++){
            float kvv=kvs[c*JD+j];
            ka += kws[o*DH+c]*kvv;
            va += vws[o*DH+c]*kvv;
        }
        g_k[bg*DH*JD + i] = ka;
        g_v[bg*DH*JD + i] = va;
    }
}

// ---------------- 5) CPB bias MLP — tf32 tensor-core version ----------------
// Block: 128 points (M), 128 hidden (N), K=128. 8 warps (4m x 2n), warp tile 32x64.
// Fuses layer1 (h1 -> smem), layer2 (mma), layer3 (relu-dot-w3 epilogue + reduce).
__global__ void __launch_bounds__(256) k_cpb(
        const float* __restrict__ w1, const float* __restrict__ b1,
        const float* __restrict__ w2, const float* __restrict__ b2,
        const float* __restrict__ w3, const float* __restrict__ b3){
    extern __shared__ float sm[];
    float* Hs  = sm;                 // [m][k] pad 132
    float* Ws  = Hs + 128*132;       // [k][n] pad 132
    float* red = Ws + 128*132;       // [128][2]
    float* f0s = red + 256;
    float* f1s = f0s + 128;
    float* b2s = f1s + 128;
    float* w3s = b2s + 128;
    int tid = threadIdx.x;
    int pt0 = blockIdx.x*128;
    int bg  = pt0>>16;
    if(tid<128){
        int pt = pt0 + tid;
        int i = (pt>>6)&1023;
        int j = pt&63;
        float qx = 2.0f*(float)(i&31)*(1.0f/31.0f) - 1.0f;
        float qy = 2.0f*(float)(i>>5)*(1.0f/31.0f) - 1.0f;
        float p0 = qx - g_grid[(bg*JD+j)*2];
        float p1 = qy - g_grid[(bg*JD+j)*2+1];
        f0s[tid] = copysignf(log1pf(fabsf(p0)), p0);
        f1s[tid] = copysignf(log1pf(fabsf(p1)), p1);
        b2s[tid] = b2[tid];
        w3s[tid] = w3[tid];
    }
    for(int idx=tid;idx<128*128;idx+=256){
        int k=idx>>7, n=idx&127;
        Ws[k*132+n] = __uint_as_float(f2tf(w2[k*128+n]));
    }
    __syncthreads();
    for(int idx=tid;idx<128*128;idx+=256){
        int m=idx>>7, k=idx&127;
        float h = f0s[m]*w1[k] + f1s[m]*w1[128+k] + b1[k];
        Hs[m*132+k] = __uint_as_float(f2tf(fmaxf(h,0.f)));
    }
    __syncthreads();

    int lane = tid&31, wid = tid>>5;
    int wm = wid>>1, wn = wid&1;
    int mbase = wm*32, nbase = wn*64;
    int g = lane>>2, t = lane&3;
    float acc[2][8][4];
    #pragma unroll
    for(int a=0;a<2;a++){ 
        #pragma unroll
        for(int nn=0;nn<8;nn++){ 
            #pragma unroll
            for(int cc=0;cc<4;cc++) acc[a][nn][cc]=0.f; } }

    #pragma unroll 2
    for(int k0=0;k0<128;k0+=8){
        uint32_t af[2][4];
        #pragma unroll
        for(int mt=0;mt<2;mt++){
            const float* hp = Hs + (mbase + mt*16 + g)*132 + k0 + t;
            af[mt][0] = __float_as_uint(hp[0]);
            af[mt][1] = __float_as_uint(hp[8*132]);
            af[mt][2] = __float_as_uint(hp[4]);
            af[mt][3] = __float_as_uint(hp[8*132+4]);
        }
        uint32_t bf[8][2];
        #pragma unroll
        for(int nt=0;nt<8;nt++){
            const float* wp = Ws + (k0+t)*132 + nbase + nt*8 + g;
            bf[nt][0] = __float_as_uint(wp[0]);
            bf[nt][1] = __float_as_uint(wp[4*132]);
        }
        #pragma unroll
        for(int mt=0;mt<2;mt++){
            #pragma unroll
            for(int nt=0;nt<8;nt++) mma_tf32(acc[mt][nt], af[mt], bf[nt]);
        }
    }
    // layer3 epilogue: relu(h2+b2)*w3, reduce over n
    #pragma unroll
    for(int mt=0;mt<2;mt++){
        float pA=0.f, pB=0.f;   // rows g, g+8
        #pragma unroll
        for(int nt=0;nt<8;nt++){
            int n = nbase + nt*8 + 2*t;
            float ba=b2s[n], bb=b2s[n+1], wa=w3s[n], wb=w3s[n+1];
            pA += fmaxf(acc[mt][nt][0]+ba,0.f)*wa + fmaxf(acc[mt][nt][1]+bb,0.f)*wb;
            pB += fmaxf(acc[mt][nt][2]+ba,0.f)*wa + fmaxf(acc[mt][nt][3]+bb,0.f)*wb;
        }
        pA += __shfl_xor_sync(0xffffffffu, pA, 1);
        pA += __shfl_xor_sync(0xffffffffu, pA, 2);
        pB += __shfl_xor_sync(0xffffffffu, pB, 1);
        pB += __shfl_xor_sync(0xffffffffu, pB, 2);
        if(t==0){
            red[(mbase+mt*16+g)*2 + wn]   = pA;
            red[(mbase+mt*16+8+g)*2 + wn] = pB;
        }
    }
    __syncthreads();
    if(tid<128) g_bias[pt0+tid] = b3[0] + red[tid*2] + red[tid*2+1];
}

// ---------------- 6) attention ----------------
__global__ void k_attn(){
    __shared__ float ks[DH*JD];
    __shared__ float vs[DH*JD];
    int bg=blockIdx.y, it=blockIdx.x, tid=threadIdx.x;
    int b=bg>>3, g=bg&7;
    for(int i=tid;i<DH*JD;i+=128){ ks[i]=g_k[bg*DH*JD+i]; vs[i]=g_v[bg*DH*JD+i]; }
    __syncthreads();
    int i = it*128 + tid;
    const float* qp = g_q + (b*NC+g*DH)*HW + i;
    float sim[JD];
    #pragma unroll
    for(int j=0;j<JD;j++) sim[j]=0.f;
    for(int d=0;d<DH;d++){
        float qv = qp[d*HW];
        #pragma unroll
        for(int j=0;j<JD;j++) sim[j] += qv*ks[d*JD+j];
    }
    const float scale = 0.125f;
    const float* bp = g_bias + (bg*HW + i)*JD;
    float m=-1e30f;
    #pragma unroll
    for(int j=0;j<JD;j++){ sim[j] = sim[j]*scale + bp[j]; m=fmaxf(m,sim[j]); }
    float ssum=0.f;
    #pragma unroll
    for(int j=0;j<JD;j++){ sim[j]=expf(sim[j]-m); ssum+=sim[j]; }
    float inv = 1.0f/ssum;
    float* op = g_attn + (b*NC+g*DH)*HW + i;
    for(int d=0;d<DH;d++){
        float a=0.f;
        #pragma unroll
        for(int j=0;j<JD;j++) a += sim[j]*vs[d*JD+j];
        op[d*HW] = a*inv;
    }
}

// ------------- shared mma-GEMM macro body: 128x128 tile, K staged by 32 -------------
#define GEMM_STAGE(KTOT, A_EXPR, B_EXPR)                                         \
    for(int k0=0;k0<(KTOT);k0+=32){                                              \
        for(int idx=tid;idx<4096;idx+=256){                                      \
            int m=idx>>5, k=idx&31;                                              \
            As[m*36+k] = __uint_as_float(f2tf(A_EXPR));                          \
        }                                                                        \
        for(int idx=tid;idx<4096;idx+=256){                                      \
            int k=idx>>7, n=idx&127;                                             \
            Bs[k*132+n] = __uint_as_float(f2tf(B_EXPR));                         \
        }                                                                        \
        __syncthreads();                                                         \
        _Pragma("unroll")                                                        \
        for(int kc=0;kc<32;kc+=8){                                               \
            uint32_t af[2][4];                                                   \
            _Pragma("unroll")                                                    \
            for(int mt=0;mt<2;mt++){                                             \
                const float* ap = As + (mbase + mt*16 + g)*36 + kc + t;          \
                af[mt][0] = __float_as_uint(ap[0]);                              \
                af[mt][1] = __float_as_uint(ap[8*36]);                           \
                af[mt][2] = __float_as_uint(ap[4]);                              \
                af[mt][3] = __float_as_uint(ap[8*36+4]);                         \
            }                                                                    \
            uint32_t bf[8][2];                                                   \
            _Pragma("unroll")                                                    \
            for(int nt=0;nt<8;nt++){                                             \
                const float* bp = Bs + (kc+t)*132 + nbase + nt*8 + g;            \
                bf[nt][0] = __float_as_uint(bp[0]);                              \
                bf[nt][1] = __float_as_uint(bp[4*132]);                          \
            }                                                                    \
            _Pragma("unroll")                                                    \
            for(int mt=0;mt<2;mt++){                                             \
                _Pragma("unroll")                                                \
                for(int nt=0;nt<8;nt++) mma_tf32(acc[mt][nt], af[mt], bf[nt]);   \
            }                                                                    \
        }                                                                        \
        __syncthreads();                                                         \
    }

#define GEMM_PROLOG                                                              \
    __shared__ float As[128*36];                                                 \
    __shared__ float Bs[32*132];                                                 \
    int m0 = blockIdx.y*128, n0 = blockIdx.x*128;                                \
    int b = n0>>10, p0 = n0&1023;                                                \
    int tid=threadIdx.x, lane=tid&31, wid=tid>>5;                                \
    int mbase = (wid>>1)*32, nbase = (wid&1)*64;                                 \
    int g=lane>>2, t=lane&3;                                                     \
    float acc[2][8][4];                                                          \
    _Pragma("unroll")                                                            \
    for(int a=0;a<2;a++){                                                        \
        _Pragma("unroll")                                                        \
        for(int nn=0;nn<8;nn++){                                                 \
            _Pragma("unroll")                                                    \
            for(int cc=0;cc<4;cc++) acc[a][nn][cc]=0.f; } }

// ---------------- 7) out projection + residual + fused bn2 (mma) ----------------
__global__ void __launch_bounds__(256) k_outproj(
        const float* __restrict__ ow, const float* __restrict__ ob,
        const float* __restrict__ x, const float* __restrict__ g2,
        const float* __restrict__ bb2){
    GEMM_PROLOG
    GEMM_STAGE(512,
        ow[(m0+m)*512 + k0+k],
        g_attn[(b*NC + k0+k)*HW + p0+n])
    #pragma unroll
    for(int mt=0;mt<2;mt++){
        int mr = m0 + mbase + mt*16 + g;
        float bi0=ob[mr], bi1=ob[mr+8];
        float s0=g2[mr]*rsqrtf(1.0f+EPSBN), s1=g2[mr+8]*rsqrtf(1.0f+EPSBN);
        float c0=bb2[mr], c1=bb2[mr+8];
        #pragma unroll
        for(int nt=0;nt<8;nt++){
            int n = p0 + nbase + nt*8 + 2*t;
            int off0 = (b*NC + mr)*HW + n;
            int off1 = (b*NC + mr+8)*HW + n;
            float2 xv0 = *(const float2*)&x[off0];
            float2 xv1 = *(const float2*)&x[off1];
            float2 v0 = { xv0.x + acc[mt][nt][0] + bi0, xv0.y + acc[mt][nt][1] + bi0 };
            float2 v1 = { xv1.x + acc[mt][nt][2] + bi1, xv1.y + acc[mt][nt][3] + bi1 };
            *(float2*)&g_x2[off0] = v0;
            *(float2*)&g_x2[off1] = v1;
            float2 n0v = { v0.x*s0+c0, v0.y*s0+c0 };
            float2 n1v = { v1.x*s1+c1, v1.y*s1+c1 };
            *(float2*)&g_xn2[off0] = n0v;
            *(float2*)&g_xn2[off1] = n1v;
        }
    }
}

// ---------------- 8) MLP conv1 (mma) ----------------
__global__ void __launch_bounds__(256) k_mlp1(
        const float* __restrict__ w, const float* __restrict__ bias){
    GEMM_PROLOG
    GEMM_STAGE(512,
        w[(m0+m)*512 + k0+k],
        g_xn2[(b*NC + k0+k)*HW + p0+n])
    #pragma unroll
    for(int mt=0;mt<2;mt++){
        int mr = m0 + mbase + mt*16 + g;
        float bi0=bias[mr], bi1=bias[mr+8];
        #pragma unroll
        for(int nt=0;nt<8;nt++){
            int n = p0 + nbase + nt*8 + 2*t;
            float2 v0 = { gelu_exact(acc[mt][nt][0]+bi0), gelu_exact(acc[mt][nt][1]+bi0) };
            float2 v1 = { gelu_exact(acc[mt][nt][2]+bi1), gelu_exact(acc[mt][nt][3]+bi1) };
            *(float2*)&g_h1[(b*2048 + mr)*HW + n]   = v0;
            *(float2*)&g_h1[(b*2048 + mr+8)*HW + n] = v1;
        }
    }
}

// ---------------- 9) MLP conv2 + residual (mma) ----------------
__global__ void __launch_bounds__(256) k_mlp2(
        const float* __restrict__ w, const float* __restrict__ bias,
        float* __restrict__ out){
    GEMM_PROLOG
    GEMM_STAGE(2048,
        w[(m0+m)*2048 + k0+k],
        g_h1[(b*2048 + k0+k)*HW + p0+n])
    #pragma unroll
    for(int mt=0;mt<2;mt++){
        int mr = m0 + mbase + mt*16 + g;
        float bi0=bias[mr], bi1=bias[mr+8];
        #pragma unroll
        for(int nt=0;nt<8;nt++){
            int n = p0 + nbase + nt*8 + 2*t;
            int off0 = (b*NC + mr)*HW + n;
            int off1 = (b*NC + mr+8)*HW + n;
            float2 r0 = *(const float2*)&g_x2[off0];
            float2 r1 = *(const float2*)&g_x2[off1];
            float2 v0 = { r0.x + acc[mt][nt][0] + bi0, r0.y + acc[mt][nt][1] + bi0 };
            float2 v1 = { r1.x + acc[mt][nt][2] + bi1, r1.y + acc[mt][nt][3] + bi1 };
            *(float2*)&out[off0] = v0;
            *(float2*)&out[off1] = v1;
        }
    }
}

// ---------------- launch ----------------
extern "C" void kernel_launch(void* const* d_in, const int* in_sizes, int n_in,
                              void* d_out, int out_size){
    const float* x    = (const float*)d_in[0];
    const float* bn1g = (const float*)d_in[1];
    const float* bn1b = (const float*)d_in[2];
    const float* bn2g = (const float*)d_in[3];
    const float* bn2b = (const float*)d_in[4];
    const float* qw   = (const float*)d_in[5];
    const float* kw   = (const float*)d_in[6];
    const float* vw   = (const float*)d_in[7];
    const float* ow   = (const float*)d_in[8];
    const float* obv  = (const float*)d_in[9];
    const float* dw   = (const float*)d_in[10];
    const float* dwb  = (const float*)d_in[11];
    const float* pw   = (const float*)d_in[12];
    const float* cw1  = (const float*)d_in[13];
    const float* cb1  = (const float*)d_in[14];
    const float* cw2  = (const float*)d_in[15];
    const float* cb2  = (const float*)d_in[16];
    const float* cw3  = (const float*)d_in[17];
    const float* cb3  = (const float*)d_in[18];
    const float* mw1  = (const float*)d_in[19];
    const float* mb1  = (const float*)d_in[20];
    const float* mw2  = (const float*)d_in[21];
    const float* mb2  = (const float*)d_in[22];
    float* out = (float*)d_out;

    const int cpb_smem = (128*132*2 + 256 + 4*128) * 4;   // 138240 B
    cudaFuncSetAttribute(k_cpb, cudaFuncAttributeMaxDynamicSharedMemorySize, cpb_smem);

    k_bn1    <<<4096,256>>>(x,bn1g,bn1b);
    k_qproj  <<<dim3(8,16),128>>>(qw);
    k_offsets<<<16,64>>>(dw,dwb,pw);
    k_sample <<<16,256>>>(kw,vw);
    k_cpb    <<<8192,256,cpb_smem>>>(cw1,cb1,cw2,cb2,cw3,cb3);
    k_attn   <<<dim3(8,16),128>>>();
    k_outproj<<<dim3(16,4),256>>>(ow,obv,x,bn2g,bn2b);
    k_mlp1   <<<dim3(16,16),256>>>(mw1,mb1);
    k_mlp2   <<<dim3(16,4),256>>>(mw2,mb2,out);
}

// round 3
// speedup vs baseline: 2.7514x; 1.7231x over previous
#include <cuda_runtime.h>
#include <cstdint>

#define NB 2
#define NC 512
#define NH 32
#define NW 32
#define HW 1024
#define NG 8
#define DH 64
#define BG 16      // NB*NG
#define JD 64      // Hd*Wd = 8*8
#define EPSBN 1e-5f

// ---------------- scratch ----------------
__device__ float g_xn[NB*NC*HW];
__device__ float g_q[NB*NC*HW];
__device__ float g_grid[BG*JD*2];
__device__ float g_k[BG*DH*JD];
__device__ float g_v[BG*DH*JD];
__device__ float g_bias[BG*HW*JD];
__device__ float g_attn[NB*NC*HW];
__device__ float g_x2[NB*NC*HW];
__device__ float g_xn2[NB*NC*HW];
__device__ float g_h1[NB*2048*HW];

__device__ __forceinline__ float gelu_exact(float x){
    return 0.5f*x*(1.0f+erff(x*0.7071067811865476f));
}
__device__ __forceinline__ uint32_t f2tf(float v){
    uint32_t r; asm("cvt.rna.tf32.f32 %0, %1;" : "=r"(r) : "f"(v)); return r;
}
__device__ __forceinline__ float tfr(float v){ return __uint_as_float(f2tf(v)); }
__device__ __forceinline__ void mma_tf32(float c[4], const uint32_t a[4], const uint32_t b[2]){
    asm volatile("mma.sync.aligned.m16n8k8.row.col.f32.tf32.tf32.f32 "
        "{%0,%1,%2,%3}, {%4,%5,%6,%7}, {%8,%9}, {%0,%1,%2,%3};"
        : "+f"(c[0]),"+f"(c[1]),"+f"(c[2]),"+f"(c[3])
        : "r"(a[0]),"r"(a[1]),"r"(a[2]),"r"(a[3]),"r"(b[0]),"r"(b[1]));
}

// ---------------- 1) bn1 ----------------
__global__ void k_bn1(const float* __restrict__ x, const float* __restrict__ g1,
                      const float* __restrict__ b1){
    int idx = blockIdx.x*256 + threadIdx.x;
    int c = (idx>>10)&(NC-1);
    float s = g1[c]*rsqrtf(1.0f+EPSBN);
    g_xn[idx] = x[idx]*s + b1[c];
}

// ---------------- 2) q grouped 1x1 conv ----------------
__global__ void k_qproj(const float* __restrict__ qw){
    __shared__ float ws[DH*DH];
    __shared__ float xs[DH*128];
    int bg = blockIdx.y; int b = bg>>3, g = bg&7;
    int p0 = blockIdx.x*128;
    int tid = threadIdx.x;
    const float* wsrc = qw + g*DH*DH;
    for(int i=tid;i<DH*DH;i+=128) ws[i]=wsrc[i];
    const float* xsrc = g_xn + (b*NC + g*DH)*HW + p0;
    for(int i=tid;i<DH*128;i+=128){ int c=i>>7, col=i&127; xs[c*128+col]=xsrc[c*HW+col]; }
    __syncthreads();
    float acc[DH];
    #pragma unroll
    for(int o=0;o<DH;o++) acc[o]=0.f;
    for(int c=0;c<DH;c++){
        float xv = xs[c*128+tid];
        #pragma unroll
        for(int o=0;o<DH;o++) acc[o] += ws[o*DH+c]*xv;
    }
    float* qdst = g_q + (b*NC + g*DH)*HW + p0 + tid;
    #pragma unroll
    for(int o=0;o<DH;o++) qdst[o*HW]=acc[o];
}

// ---------------- 3) offsets ----------------
__global__ void k_offsets(const float* __restrict__ dw, const float* __restrict__ dwb,
                          const float* __restrict__ pw){
    __shared__ float dws[DH*36];
    int bg = blockIdx.x; int tid = threadIdx.x;
    for(int i=tid;i<DH*36;i+=64) dws[i]=dw[i];
    __syncthreads();
    int b=bg>>3, g=bg&7;
    int oy=tid>>3, ox=tid&7;
    const float* qp = g_q + (b*NC+g*DH)*HW;
    float a0=0.f, a1=0.f;
    for(int ch=0;ch<DH;ch++){
        const float* qc = qp + ch*HW;
        float s=0.f;
        #pragma unroll
        for(int ky=0;ky<6;ky++){
            int iy = oy*4-1+ky;
            if(iy<0||iy>=NH) continue;
            #pragma unroll
            for(int kx=0;kx<6;kx++){
                int ix = ox*4-1+kx;
                if(ix<0||ix>=NW) continue;
                s += qc[iy*NW+ix]*dws[ch*36+ky*6+kx];
            }
        }
        s = gelu_exact(s + dwb[ch]);
        a0 += s*pw[ch];
        a1 += s*pw[DH+ch];
    }
    float vx = (float)ox + tanhf(a0)*4.0f;
    float vy = (float)oy + tanhf(a1)*4.0f;
    g_grid[(bg*JD+tid)*2+0] = 2.0f*vx/7.0f - 1.0f;
    g_grid[(bg*JD+tid)*2+1] = 2.0f*vy/7.0f - 1.0f;
}

// ---------------- 4) grid_sample + k/v grouped conv (split over 4 o-chunks) ----------------
__global__ void k_sample(const float* __restrict__ kw, const float* __restrict__ vw){
    __shared__ float kvs[DH*JD];
    __shared__ float kws[DH*DH];
    __shared__ float vws[DH*DH];
    int bg=blockIdx.x, gy=blockIdx.y, tid=threadIdx.x;
    int b=bg>>3, g=bg&7;
    for(int i=tid;i<DH*DH;i+=256){ kws[i]=kw[g*DH*DH+i]; vws[i]=vw[g*DH*DH+i]; }
    const float* img = g_xn + (b*NC+g*DH)*HW;
    for(int i=tid;i<DH*JD;i+=256){
        int c=i>>6, j=i&63;
        float nx=g_grid[(bg*JD+j)*2], ny=g_grid[(bg*JD+j)*2+1];
        float gx=(nx+1.0f)*16.0f-0.5f;
        float gy2=(ny+1.0f)*16.0f-0.5f;
        float x0f=floorf(gx), y0f=floorf(gy2);
        float wx=gx-x0f, wy=gy2-y0f;
        int x0=(int)x0f, y0=(int)y0f;
        const float* im=img+c*HW;
        float v00=0.f,v01=0.f,v10=0.f,v11=0.f;
        bool xi0 = (x0>=0)&&(x0<NW), xi1 = (x0+1>=0)&&(x0+1<NW);
        bool yi0 = (y0>=0)&&(y0<NH), yi1 = (y0+1>=0)&&(y0+1<NH);
        if(yi0){ if(xi0) v00=im[y0*NW+x0]; if(xi1) v01=im[y0*NW+x0+1]; }
        if(yi1){ if(xi0) v10=im[(y0+1)*NW+x0]; if(xi1) v11=im[(y0+1)*NW+x0+1]; }
        kvs[c*JD+j] = v00*(1.f-wx)*(1.f-wy)+v01*wx*(1.f-wy)+v10*(1.f-wx)*wy+v11*wx*wy;
    }
    __syncthreads();
    for(int i=tid;i<16*JD;i+=256){
        int o=gy*16 + (i>>6), j=i&63;
        float ka=0.f,va=0.f;
        for(int c=0;c<DH;c++){
            float kvv=kvs[c*JD+j];
            ka += kws[o*DH+c]*kvv;
            va += vws[o*DH+c]*kvv;
        }
        g_k[bg*DH*JD + o*JD + j] = ka;
        g_v[bg*DH*JD + o*JD + j] = va;
    }
}

// ---------------- 5) CPB bias MLP — 256 points/block, 512 threads, 16 warps ----------------
__global__ void __launch_bounds__(512,1) k_cpb(
        const float* __restrict__ w1, const float* __restrict__ b1,
        const float* __restrict__ w2, const float* __restrict__ b2,
        const float* __restrict__ w3, const float* __restrict__ b3){
    extern __shared__ float sm[];
    float* Hs  = sm;                 // [256][132]
    float* Ws  = Hs + 256*132;       // [128][132]
    float* red = Ws + 128*132;       // [256][4]
    float* f0s = red + 1024;         // 256
    float* f1s = f0s + 256;          // 256
    float* b2s = f1s + 256;          // 128
    float* w3s = b2s + 128;          // 128
    float* w1s = w3s + 128;          // 256
    float* b1s = w1s + 256;          // 128
    int tid = threadIdx.x;
    int pt0 = blockIdx.x*256;
    int bg  = pt0>>16;
    if(tid<256){
        int pt = pt0 + tid;
        int i = (pt>>6)&1023;
        int j = pt&63;
        float qx = 2.0f*(float)(i&31)*(1.0f/31.0f) - 1.0f;
        float qy = 2.0f*(float)(i>>5)*(1.0f/31.0f) - 1.0f;
        float p0 = qx - g_grid[(bg*JD+j)*2];
        float p1 = qy - g_grid[(bg*JD+j)*2+1];
        f0s[tid] = copysignf(log1pf(fabsf(p0)), p0);
        f1s[tid] = copysignf(log1pf(fabsf(p1)), p1);
        w1s[tid] = w1[tid];
    }
    if(tid<128){ b1s[tid]=b1[tid]; b2s[tid]=b2[tid]; w3s[tid]=w3[tid]; }
    // stage w2 (float4, tf32-rounded)
    #pragma unroll
    for(int it=0; it<8; it++){
        int idx = tid + it*512;           // 4096 float4 groups
        int k = idx>>5, n4 = (idx&31)*4;
        float4 v = *(const float4*)&w2[k*128 + n4];
        *(float4*)&Ws[k*132 + n4] = make_float4(tfr(v.x),tfr(v.y),tfr(v.z),tfr(v.w));
    }
    __syncthreads();
    // layer1 -> Hs (float4)
    #pragma unroll
    for(int it=0; it<16; it++){
        int idx = tid + it*512;           // 8192 groups: m = idx>>5, k4=(idx&31)*4
        int m = idx>>5, k4 = (idx&31)*4;
        float f0 = f0s[m], f1 = f1s[m];
        float4 wv0 = *(const float4*)&w1s[k4];
        float4 wv1 = *(const float4*)&w1s[128+k4];
        float4 bv  = *(const float4*)&b1s[k4];
        float4 h;
        h.x = tfr(fmaxf(f0*wv0.x + f1*wv1.x + bv.x, 0.f));
        h.y = tfr(fmaxf(f0*wv0.y + f1*wv1.y + bv.y, 0.f));
        h.z = tfr(fmaxf(f0*wv0.z + f1*wv1.z + bv.z, 0.f));
        h.w = tfr(fmaxf(f0*wv0.w + f1*wv1.w + bv.w, 0.f));
        *(float4*)&Hs[m*132 + k4] = h;
    }
    __syncthreads();

    int lane = tid&31, wid = tid>>5;
    int g = lane>>2, t = lane&3;
    int mbase = (wid&3)*64, nbase = (wid>>2)*32;
    float acc[4][4][4];
    #pragma unroll
    for(int a=0;a<4;a++){
        #pragma unroll
        for(int nn=0;nn<4;nn++){
            #pragma unroll
            for(int cc=0;cc<4;cc++) acc[a][nn][cc]=0.f; } }

    #pragma unroll 4
    for(int kc=0;kc<16;kc++){
        int K = kc*8;
        uint32_t af[4][4];
        #pragma unroll
        for(int mt=0;mt<4;mt++){
            const float* ap = Hs + (mbase+mt*16+g)*132 + K + t;
            af[mt][0] = __float_as_uint(ap[0]);
            af[mt][1] = __float_as_uint(ap[8*132]);
            af[mt][2] = __float_as_uint(ap[4]);
            af[mt][3] = __float_as_uint(ap[8*132+4]);
        }
        uint32_t bf[4][2];
        #pragma unroll
        for(int nt=0;nt<4;nt++){
            const float* bp = Ws + (K+t)*132 + nbase + nt*8 + g;
            bf[nt][0] = __float_as_uint(bp[0]);
            bf[nt][1] = __float_as_uint(bp[4*132]);
        }
        #pragma unroll
        for(int mt=0;mt<4;mt++){
            #pragma unroll
            for(int nt=0;nt<4;nt++) mma_tf32(acc[mt][nt], af[mt], bf[nt]);
        }
    }
    // layer3 epilogue
    #pragma unroll
    for(int mt=0;mt<4;mt++){
        float pA=0.f, pB=0.f;
        #pragma unroll
        for(int nt=0;nt<4;nt++){
            int n = nbase + nt*8 + 2*t;
            float ba=b2s[n], bb=b2s[n+1], wa=w3s[n], wb=w3s[n+1];
            pA += fmaxf(acc[mt][nt][0]+ba,0.f)*wa + fmaxf(acc[mt][nt][1]+bb,0.f)*wb;
            pB += fmaxf(acc[mt][nt][2]+ba,0.f)*wa + fmaxf(acc[mt][nt][3]+bb,0.f)*wb;
        }
        pA += __shfl_xor_sync(0xffffffffu, pA, 1);
        pA += __shfl_xor_sync(0xffffffffu, pA, 2);
        pB += __shfl_xor_sync(0xffffffffu, pB, 1);
        pB += __shfl_xor_sync(0xffffffffu, pB, 2);
        if(t==0){
            int rA = mbase+mt*16+g;
            red[rA*4 + (wid>>2)]     = pA;
            red[(rA+8)*4 + (wid>>2)] = pB;
        }
    }
    __syncthreads();
    if(tid<256)
        g_bias[pt0+tid] = b3[0] + red[tid*4] + red[tid*4+1] + red[tid*4+2] + red[tid*4+3];
}

// ---------------- 6) attention ----------------
__global__ void k_attn(){
    __shared__ float ks[DH*JD];
    __shared__ float vs[DH*JD];
    int bg=blockIdx.y, it=blockIdx.x, tid=threadIdx.x;
    int b=bg>>3, g=bg&7;
    for(int i=tid;i<DH*JD;i+=128){ ks[i]=g_k[bg*DH*JD+i]; vs[i]=g_v[bg*DH*JD+i]; }
    __syncthreads();
    int i = it*128 + tid;
    const float* qp = g_q + (b*NC+g*DH)*HW + i;
    float sim[JD];
    #pragma unroll
    for(int j=0;j<JD;j++) sim[j]=0.f;
    for(int d=0;d<DH;d++){
        float qv = qp[d*HW];
        #pragma unroll
        for(int j=0;j<JD;j++) sim[j] += qv*ks[d*JD+j];
    }
    const float scale = 0.125f;
    const float* bp = g_bias + (bg*HW + i)*JD;
    float m=-1e30f;
    #pragma unroll
    for(int j=0;j<JD;j++){ sim[j] = sim[j]*scale + bp[j]; m=fmaxf(m,sim[j]); }
    float ssum=0.f;
    #pragma unroll
    for(int j=0;j<JD;j++){ sim[j]=expf(sim[j]-m); ssum+=sim[j]; }
    float inv = 1.0f/ssum;
    float* op = g_attn + (b*NC+g*DH)*HW + i;
    for(int d=0;d<DH;d++){
        float a=0.f;
        #pragma unroll
        for(int j=0;j<JD;j++) a += sim[j]*vs[d*JD+j];
        op[d*HW] = a*inv;
    }
}

// ---------------- pipelined tf32 GEMM core ----------------
// Block tile: BM x 128, BM = MT*32. 8 warps: wm = wid&1 (m), wn = wid>>1 (4 n-warps of 32).
// As: [BM][36] row-major m x k-stage(32).  Bs: [32][132].
template<int MT, int KTOT>
__device__ __forceinline__ void gemm_core(const float* __restrict__ A,
                                          const float* __restrict__ Bb,
                                          int m0, int p0,
                                          float* As, float* Bs,
                                          float (*acc)[4][4]){
    constexpr int NA = MT*32/32;     // float4 loads per thread for A stage
    constexpr int NS = KTOT/32;
    int tid=threadIdx.x, lane=tid&31, wid=tid>>5;
    int g=lane>>2, t=lane&3;
    int mbase=(wid&1)*MT*16, nbase=(wid>>1)*32;
    float4 ra[NA], rb[4];
    #pragma unroll
    for(int ia=0; ia<NA; ia++){
        int idx = tid + ia*256;
        ra[ia] = *(const float4*)&A[(m0+(idx>>3))*KTOT + (idx&7)*4];
    }
    #pragma unroll
    for(int ib=0; ib<4; ib++){
        int idx = tid + ib*256;
        rb[ib] = *(const float4*)&Bb[(idx>>5)*HW + p0 + (idx&31)*4];
    }
    for(int s=0; s<NS; s++){
        if(s) __syncthreads();
        #pragma unroll
        for(int ia=0; ia<NA; ia++){
            int idx = tid + ia*256;
            float4 v = ra[ia];
            *(float4*)&As[(idx>>3)*36 + (idx&7)*4] =
                make_float4(tfr(v.x),tfr(v.y),tfr(v.z),tfr(v.w));
        }
        #pragma unroll
        for(int ib=0; ib<4; ib++){
            int idx = tid + ib*256;
            float4 v = rb[ib];
            *(float4*)&Bs[(idx>>5)*132 + (idx&31)*4] =
                make_float4(tfr(v.x),tfr(v.y),tfr(v.z),tfr(v.w));
        }
        __syncthreads();
        if(s+1<NS){
            int k0 = (s+1)*32;
            #pragma unroll
            for(int ia=0; ia<NA; ia++){
                int idx = tid + ia*256;
                ra[ia] = *(const float4*)&A[(m0+(idx>>3))*KTOT + k0 + (idx&7)*4];
            }
            #pragma unroll
            for(int ib=0; ib<4; ib++){
                int idx = tid + ib*256;
                rb[ib] = *(const float4*)&Bb[(k0+(idx>>5))*HW + p0 + (idx&31)*4];
            }
        }
        #pragma unroll
        for(int kc=0;kc<4;kc++){
            int K = kc*8;
            uint32_t af[MT][4];
            #pragma unroll
            for(int mt=0;mt<MT;mt++){
                const float* ap = As + (mbase+mt*16+g)*36 + K + t;
                af[mt][0] = __float_as_uint(ap[0]);
                af[mt][1] = __float_as_uint(ap[8*36]);
                af[mt][2] = __float_as_uint(ap[4]);
                af[mt][3] = __float_as_uint(ap[8*36+4]);
            }
            uint32_t bf[4][2];
            #pragma unroll
            for(int nt=0;nt<4;nt++){
                const float* bp = Bs + (K+t)*132 + nbase + nt*8 + g;
                bf[nt][0] = __float_as_uint(bp[0]);
                bf[nt][1] = __float_as_uint(bp[4*132]);
            }
            #pragma unroll
            for(int mt=0;mt<MT;mt++){
                #pragma unroll
                for(int nt=0;nt<4;nt++) mma_tf32(acc[mt][nt], af[mt], bf[nt]);
            }
        }
    }
}

// ---------------- 7) out projection + residual + fused bn2 ----------------
__global__ void __launch_bounds__(256,2) k_outproj(
        const float* __restrict__ ow, const float* __restrict__ ob,
        const float* __restrict__ x, const float* __restrict__ g2,
        const float* __restrict__ bb2){
    __shared__ float As[64*36];
    __shared__ float Bs[32*132];
    int m0 = blockIdx.y*64, n0 = blockIdx.x*128;
    int b = n0>>10, p0 = n0&1023;
    float acc[2][4][4];
    #pragma unroll
    for(int a=0;a<2;a++){ 
        #pragma unroll
        for(int nn=0;nn<4;nn++){ 
            #pragma unroll
            for(int cc=0;cc<4;cc++) acc[a][nn][cc]=0.f; } }
    gemm_core<2,512>(ow, g_attn + b*NC*HW, m0, p0, As, Bs, acc);
    int tid=threadIdx.x, lane=tid&31, wid=tid>>5;
    int g=lane>>2, t=lane&3;
    int mbase=(wid&1)*32, nbase=(wid>>1)*32;
    #pragma unroll
    for(int mt=0;mt<2;mt++){
        int mr = m0 + mbase + mt*16 + g;
        float bi0=ob[mr], bi1=ob[mr+8];
        float s0=g2[mr]*rsqrtf(1.0f+EPSBN), s1=g2[mr+8]*rsqrtf(1.0f+EPSBN);
        float c0=bb2[mr], c1=bb2[mr+8];
        #pragma unroll
        for(int nt=0;nt<4;nt++){
            int n = p0 + nbase + nt*8 + 2*t;
            int off0 = (b*NC + mr)*HW + n;
            int off1 = (b*NC + mr+8)*HW + n;
            float2 xv0 = *(const float2*)&x[off0];
            float2 xv1 = *(const float2*)&x[off1];
            float2 v0 = { xv0.x + acc[mt][nt][0] + bi0, xv0.y + acc[mt][nt][1] + bi0 };
            float2 v1 = { xv1.x + acc[mt][nt][2] + bi1, xv1.y + acc[mt][nt][3] + bi1 };
            *(float2*)&g_x2[off0] = v0;
            *(float2*)&g_x2[off1] = v1;
            float2 n0v = { v0.x*s0+c0, v0.y*s0+c0 };
            float2 n1v = { v1.x*s1+c1, v1.y*s1+c1 };
            *(float2*)&g_xn2[off0] = n0v;
            *(float2*)&g_xn2[off1] = n1v;
        }
    }
}

// ---------------- 8) MLP conv1 ----------------
__global__ void __launch_bounds__(256) k_mlp1(
        const float* __restrict__ w, const float* __restrict__ bias){
    __shared__ float As[128*36];
    __shared__ float Bs[32*132];
    int m0 = blockIdx.y*128, n0 = blockIdx.x*128;
    int b = n0>>10, p0 = n0&1023;
    float acc[4][4][4];
    #pragma unroll
    for(int a=0;a<4;a++){ 
        #pragma unroll
        for(int nn=0;nn<4;nn++){ 
            #pragma unroll
            for(int cc=0;cc<4;cc++) acc[a][nn][cc]=0.f; } }
    gemm_core<4,512>(w, g_xn2 + b*NC*HW, m0, p0, As, Bs, acc);
    int tid=threadIdx.x, lane=tid&31, wid=tid>>5;
    int g=lane>>2, t=lane&3;
    int mbase=(wid&1)*64, nbase=(wid>>1)*32;
    #pragma unroll
    for(int mt=0;mt<4;mt++){
        int mr = m0 + mbase + mt*16 + g;
        float bi0=bias[mr], bi1=bias[mr+8];
        #pragma unroll
        for(int nt=0;nt<4;nt++){
            int n = p0 + nbase + nt*8 + 2*t;
            float2 v0 = { gelu_exact(acc[mt][nt][0]+bi0), gelu_exact(acc[mt][nt][1]+bi0) };
            float2 v1 = { gelu_exact(acc[mt][nt][2]+bi1), gelu_exact(acc[mt][nt][3]+bi1) };
            *(float2*)&g_h1[(b*2048 + mr)*HW + n]   = v0;
            *(float2*)&g_h1[(b*2048 + mr+8)*HW + n] = v1;
        }
    }
}

// ---------------- 9) MLP conv2 + residual ----------------
__global__ void __launch_bounds__(256,2) k_mlp2(
        const float* __restrict__ w, const float* __restrict__ bias,
        float* __restrict__ out){
    __shared__ float As[64*36];
    __shared__ float Bs[32*132];
    int m0 = blockIdx.y*64, n0 = blockIdx.x*128;
    int b = n0>>10, p0 = n0&1023;
    float acc[2][4][4];
    #pragma unroll
    for(int a=0;a<2;a++){ 
        #pragma unroll
        for(int nn=0;nn<4;nn++){ 
            #pragma unroll
            for(int cc=0;cc<4;cc++) acc[a][nn][cc]=0.f; } }
    gemm_core<2,2048>(w, g_h1 + b*2048*HW, m0, p0, As, Bs, acc);
    int tid=threadIdx.x, lane=tid&31, wid=tid>>5;
    int g=lane>>2, t=lane&3;
    int mbase=(wid&1)*32, nbase=(wid>>1)*32;
    #pragma unroll
    for(int mt=0;mt<2;mt++){
        int mr = m0 + mbase + mt*16 + g;
        float bi0=bias[mr], bi1=bias[mr+8];
        #pragma unroll
        for(int nt=0;nt<4;nt++){
            int n = p0 + nbase + nt*8 + 2*t;
            int off0 = (b*NC + mr)*HW + n;
            int off1 = (b*NC + mr+8)*HW + n;
            float2 r0 = *(const float2*)&g_x2[off0];
            float2 r1 = *(const float2*)&g_x2[off1];
            float2 v0 = { r0.x + acc[mt][nt][0] + bi0, r0.y + acc[mt][nt][1] + bi0 };
            float2 v1 = { r1.x + acc[mt][nt][2] + bi1, r1.y + acc[mt][nt][3] + bi1 };
            *(float2*)&out[off0] = v0;
            *(float2*)&out[off1] = v1;
        }
    }
}

// ---------------- launch ----------------
extern "C" void kernel_launch(void* const* d_in, const int* in_sizes, int n_in,
                              void* d_out, int out_size){
    const float* x    = (const float*)d_in[0];
    const float* bn1g = (const float*)d_in[1];
    const float* bn1b = (const float*)d_in[2];
    const float* bn2g = (const float*)d_in[3];
    const float* bn2b = (const float*)d_in[4];
    const float* qw   = (const float*)d_in[5];
    const float* kw   = (const float*)d_in[6];
    const float* vw   = (const float*)d_in[7];
    const float* ow   = (const float*)d_in[8];
    const float* obv  = (const float*)d_in[9];
    const float* dw   = (const float*)d_in[10];
    const float* dwb  = (const float*)d_in[11];
    const float* pw   = (const float*)d_in[12];
    const float* cw1  = (const float*)d_in[13];
    const float* cb1  = (const float*)d_in[14];
    const float* cw2  = (const float*)d_in[15];
    const float* cb2  = (const float*)d_in[16];
    const float* cw3  = (const float*)d_in[17];
    const float* cb3  = (const float*)d_in[18];
    const float* mw1  = (const float*)d_in[19];
    const float* mb1  = (const float*)d_in[20];
    const float* mw2  = (const float*)d_in[21];
    const float* mb2  = (const float*)d_in[22];
    float* out = (float*)d_out;

    // cpb dynamic smem: Hs 256*132 + Ws 128*132 + red 1024 + f0/f1 512 + b2/w3 256 + w1 256 + b1 128
    const int cpb_smem = (256*132 + 128*132 + 1024 + 512 + 256 + 256 + 128) * 4;
    cudaFuncSetAttribute(k_cpb, cudaFuncAttributeMaxDynamicSharedMemorySize, cpb_smem);

    k_bn1    <<<4096,256>>>(x,bn1g,bn1b);
    k_qproj  <<<dim3(8,16),128>>>(qw);
    k_offsets<<<16,64>>>(dw,dwb,pw);
    k_sample <<<dim3(16,4),256>>>(kw,vw);
    k_cpb    <<<4096,512,cpb_smem>>>(cw1,cb1,cw2,cb2,cw3,cb3);
    k_attn   <<<dim3(8,16),128>>>();
    k_outproj<<<dim3(16,8),256>>>(ow,obv,x,bn2g,bn2b);
    k_mlp1   <<<dim3(16,16),256>>>(mw1,mb1);
    k_mlp2   <<<dim3(16,8),256>>>(mw2,mb2,out);
}

// round 4
// speedup vs baseline: 4.8887x; 1.7769x over previous
#include <cuda_runtime.h>
#include <cstdint>

#define NB 2
#define NC 512
#define NH 32
#define NW 32
#define HW 1024
#define NG 8
#define DH 64
#define BG 16      // NB*NG
#define JD 64      // Hd*Wd = 8*8
#define EPSBN 1e-5f

// CPB feature-space table
#define TABN 129                 // grid points per dim (128 cells)
#define FMAXF 1.43f
#define TSTEP (2.0f*FMAXF/128.0f)
#define TINV  (128.0f/(2.0f*FMAXF))

// ---------------- scratch ----------------
__device__ float g_xn[NB*NC*HW];
__device__ float g_q[NB*NC*HW];
__device__ float g_grid[BG*JD*2];
__device__ float g_k[BG*DH*JD];
__device__ float g_v[BG*DH*JD];
__device__ float g_bias[BG*HW*JD];   // layout [bg][j][i]  (transposed!)
__device__ float g_attn[NB*NC*HW];
__device__ float g_x2[NB*NC*HW];
__device__ float g_xn2[NB*NC*HW];
__device__ float g_h1[NB*2048*HW];
__device__ float g_tab[TABN*TABN];   // CPB bias table over (f1,f0)

__device__ __forceinline__ float gelu_exact(float x){
    return 0.5f*x*(1.0f+erff(x*0.7071067811865476f));
}
__device__ __forceinline__ uint32_t f2tf(float v){
    uint32_t r; asm("cvt.rna.tf32.f32 %0, %1;" : "=r"(r) : "f"(v)); return r;
}
__device__ __forceinline__ float tfr(float v){ return __uint_as_float(f2tf(v)); }
__device__ __forceinline__ void mma_tf32(float c[4], const uint32_t a[4], const uint32_t b[2]){
    asm volatile("mma.sync.aligned.m16n8k8.row.col.f32.tf32.tf32.f32 "
        "{%0,%1,%2,%3}, {%4,%5,%6,%7}, {%8,%9}, {%0,%1,%2,%3};"
        : "+f"(c[0]),"+f"(c[1]),"+f"(c[2]),"+f"(c[3])
        : "r"(a[0]),"r"(a[1]),"r"(a[2]),"r"(a[3]),"r"(b[0]),"r"(b[1]));
}

// ---------------- 1) bn1 ----------------
__global__ void k_bn1(const float* __restrict__ x, const float* __restrict__ g1,
                      const float* __restrict__ b1){
    int idx = blockIdx.x*256 + threadIdx.x;
    int c = (idx>>10)&(NC-1);
    float s = g1[c]*rsqrtf(1.0f+EPSBN);
    g_xn[idx] = x[idx]*s + b1[c];
}

// ---------------- 2) q grouped 1x1 conv ----------------
__global__ void k_qproj(const float* __restrict__ qw){
    __shared__ float ws[DH*DH];
    __shared__ float xs[DH*128];
    int bg = blockIdx.y; int b = bg>>3, g = bg&7;
    int p0 = blockIdx.x*128;
    int tid = threadIdx.x;
    const float* wsrc = qw + g*DH*DH;
    for(int i=tid;i<DH*DH;i+=128) ws[i]=wsrc[i];
    const float* xsrc = g_xn + (b*NC + g*DH)*HW + p0;
    for(int i=tid;i<DH*128;i+=128){ int c=i>>7, col=i&127; xs[c*128+col]=xsrc[c*HW+col]; }
    __syncthreads();
    float acc[DH];
    #pragma unroll
    for(int o=0;o<DH;o++) acc[o]=0.f;
    for(int c=0;c<DH;c++){
        float xv = xs[c*128+tid];
        #pragma unroll
        for(int o=0;o<DH;o++) acc[o] += ws[o*DH+c]*xv;
    }
    float* qdst = g_q + (b*NC + g*DH)*HW + p0 + tid;
    #pragma unroll
    for(int o=0;o<DH;o++) qdst[o*HW]=acc[o];
}

// ---------------- 3) offsets ----------------
__global__ void k_offsets(const float* __restrict__ dw, const float* __restrict__ dwb,
                          const float* __restrict__ pw){
    __shared__ float dws[DH*36];
    int bg = blockIdx.x; int tid = threadIdx.x;
    for(int i=tid;i<DH*36;i+=64) dws[i]=dw[i];
    __syncthreads();
    int b=bg>>3, g=bg&7;
    int oy=tid>>3, ox=tid&7;
    const float* qp = g_q + (b*NC+g*DH)*HW;
    float a0=0.f, a1=0.f;
    for(int ch=0;ch<DH;ch++){
        const float* qc = qp + ch*HW;
        float s=0.f;
        #pragma unroll
        for(int ky=0;ky<6;ky++){
            int iy = oy*4-1+ky;
            if(iy<0||iy>=NH) continue;
            #pragma unroll
            for(int kx=0;kx<6;kx++){
                int ix = ox*4-1+kx;
                if(ix<0||ix>=NW) continue;
                s += qc[iy*NW+ix]*dws[ch*36+ky*6+kx];
            }
        }
        s = gelu_exact(s + dwb[ch]);
        a0 += s*pw[ch];
        a1 += s*pw[DH+ch];
    }
    float vx = (float)ox + tanhf(a0)*4.0f;
    float vy = (float)oy + tanhf(a1)*4.0f;
    g_grid[(bg*JD+tid)*2+0] = 2.0f*vx/7.0f - 1.0f;
    g_grid[(bg*JD+tid)*2+1] = 2.0f*vy/7.0f - 1.0f;
}

// ---------------- 4) grid_sample + k/v grouped conv ----------------
__global__ void k_sample(const float* __restrict__ kw, const float* __restrict__ vw){
    __shared__ float kvs[DH*JD];
    __shared__ float kws[DH*DH];
    __shared__ float vws[DH*DH];
    int bg=blockIdx.x, gy=blockIdx.y, tid=threadIdx.x;
    int b=bg>>3, g=bg&7;
    for(int i=tid;i<DH*DH;i+=256){ kws[i]=kw[g*DH*DH+i]; vws[i]=vw[g*DH*DH+i]; }
    const float* img = g_xn + (b*NC+g*DH)*HW;
    for(int i=tid;i<DH*JD;i+=256){
        int c=i>>6, j=i&63;
        float nx=g_grid[(bg*JD+j)*2], ny=g_grid[(bg*JD+j)*2+1];
        float gx=(nx+1.0f)*16.0f-0.5f;
        float gy2=(ny+1.0f)*16.0f-0.5f;
        float x0f=floorf(gx), y0f=floorf(gy2);
        float wx=gx-x0f, wy=gy2-y0f;
        int x0=(int)x0f, y0=(int)y0f;
        const float* im=img+c*HW;
        float v00=0.f,v01=0.f,v10=0.f,v11=0.f;
        bool xi0 = (x0>=0)&&(x0<NW), xi1 = (x0+1>=0)&&(x0+1<NW);
        bool yi0 = (y0>=0)&&(y0<NH), yi1 = (y0+1>=0)&&(y0+1<NH);
        if(yi0){ if(xi0) v00=im[y0*NW+x0]; if(xi1) v01=im[y0*NW+x0+1]; }
        if(yi1){ if(xi0) v10=im[(y0+1)*NW+x0]; if(xi1) v11=im[(y0+1)*NW+x0+1]; }
        kvs[c*JD+j] = v00*(1.f-wx)*(1.f-wy)+v01*wx*(1.f-wy)+v10*(1.f-wx)*wy+v11*wx*wy;
    }
    __syncthreads();
    for(int i=tid;i<16*JD;i+=256){
        int o=gy*16 + (i>>6), j=i&63;
        float ka=0.f,va=0.f;
        for(int c=0;c<DH;c++){
            float kvv=kvs[c*JD+j];
            ka += kws[o*DH+c]*kvv;
            va += vws[o*DH+c]*kvv;
        }
        g_k[bg*DH*JD + o*JD + j] = ka;
        g_v[bg*DH*JD + o*JD + j] = va;
    }
}

// ---------------- 5a) CPB table: evaluate MLP on 129x129 feature grid ----------------
// Same mma structure as before but M = table points; 256 pts/block, 512 threads.
__global__ void __launch_bounds__(512,1) k_tab(
        const float* __restrict__ w1, const float* __restrict__ b1,
        const float* __restrict__ w2, const float* __restrict__ b2,
        const float* __restrict__ w3, const float* __restrict__ b3){
    extern __shared__ float sm[];
    float* Hs  = sm;                 // [256][132]
    float* Ws  = Hs + 256*132;       // [128][132]
    float* red = Ws + 128*132;       // [256][4]
    float* f0s = red + 1024;
    float* f1s = f0s + 256;
    float* b2s = f1s + 256;
    float* w3s = b2s + 128;
    float* w1s = w3s + 128;
    float* b1s = w1s + 256;
    int tid = threadIdx.x;
    int pt0 = blockIdx.x*256;
    if(tid<256){
        int pt = pt0 + tid;
        int v = pt/TABN;
        int u = pt - v*TABN;
        f0s[tid] = -FMAXF + (float)u*TSTEP;
        f1s[tid] = -FMAXF + (float)v*TSTEP;
        w1s[tid] = w1[tid];
    }
    if(tid<128){ b1s[tid]=b1[tid]; b2s[tid]=b2[tid]; w3s[tid]=w3[tid]; }
    #pragma unroll
    for(int it=0; it<8; it++){
        int idx = tid + it*512;
        int k = idx>>5, n4 = (idx&31)*4;
        float4 v = *(const float4*)&w2[k*128 + n4];
        *(float4*)&Ws[k*132 + n4] = make_float4(tfr(v.x),tfr(v.y),tfr(v.z),tfr(v.w));
    }
    __syncthreads();
    #pragma unroll
    for(int it=0; it<16; it++){
        int idx = tid + it*512;
        int m = idx>>5, k4 = (idx&31)*4;
        float f0 = f0s[m], f1 = f1s[m];
        float4 wv0 = *(const float4*)&w1s[k4];
        float4 wv1 = *(const float4*)&w1s[128+k4];
        float4 bv  = *(const float4*)&b1s[k4];
        float4 h;
        h.x = tfr(fmaxf(f0*wv0.x + f1*wv1.x + bv.x, 0.f));
        h.y = tfr(fmaxf(f0*wv0.y + f1*wv1.y + bv.y, 0.f));
        h.z = tfr(fmaxf(f0*wv0.z + f1*wv1.z + bv.z, 0.f));
        h.w = tfr(fmaxf(f0*wv0.w + f1*wv1.w + bv.w, 0.f));
        *(float4*)&Hs[m*132 + k4] = h;
    }
    __syncthreads();

    int lane = tid&31, wid = tid>>5;
    int g = lane>>2, t = lane&3;
    int mbase = (wid&3)*64, nbase = (wid>>2)*32;
    float acc[4][4][4];
    #pragma unroll
    for(int a=0;a<4;a++){
        #pragma unroll
        for(int nn=0;nn<4;nn++){
            #pragma unroll
            for(int cc=0;cc<4;cc++) acc[a][nn][cc]=0.f; } }

    #pragma unroll 4
    for(int kc=0;kc<16;kc++){
        int K = kc*8;
        uint32_t af[4][4];
        #pragma unroll
        for(int mt=0;mt<4;mt++){
            const float* ap = Hs + (mbase+mt*16+g)*132 + K + t;
            af[mt][0] = __float_as_uint(ap[0]);
            af[mt][1] = __float_as_uint(ap[8*132]);
            af[mt][2] = __float_as_uint(ap[4]);
            af[mt][3] = __float_as_uint(ap[8*132+4]);
        }
        uint32_t bf[4][2];
        #pragma unroll
        for(int nt=0;nt<4;nt++){
            const float* bp = Ws + (K+t)*132 + nbase + nt*8 + g;
            bf[nt][0] = __float_as_uint(bp[0]);
            bf[nt][1] = __float_as_uint(bp[4*132]);
        }
        #pragma unroll
        for(int mt=0;mt<4;mt++){
            #pragma unroll
            for(int nt=0;nt<4;nt++) mma_tf32(acc[mt][nt], af[mt], bf[nt]);
        }
    }
    #pragma unroll
    for(int mt=0;mt<4;mt++){
        float pA=0.f, pB=0.f;
        #pragma unroll
        for(int nt=0;nt<4;nt++){
            int n = nbase + nt*8 + 2*t;
            float ba=b2s[n], bb=b2s[n+1], wa=w3s[n], wb=w3s[n+1];
            pA += fmaxf(acc[mt][nt][0]+ba,0.f)*wa + fmaxf(acc[mt][nt][1]+bb,0.f)*wb;
            pB += fmaxf(acc[mt][nt][2]+ba,0.f)*wa + fmaxf(acc[mt][nt][3]+bb,0.f)*wb;
        }
        pA += __shfl_xor_sync(0xffffffffu, pA, 1);
        pA += __shfl_xor_sync(0xffffffffu, pA, 2);
        pB += __shfl_xor_sync(0xffffffffu, pB, 1);
        pB += __shfl_xor_sync(0xffffffffu, pB, 2);
        if(t==0){
            int rA = mbase+mt*16+g;
            red[rA*4 + (wid>>2)]     = pA;
            red[(rA+8)*4 + (wid>>2)] = pB;
        }
    }
    __syncthreads();
    if(tid<256 && pt0+tid<TABN*TABN)
        g_tab[pt0+tid] = b3[0] + red[tid*4] + red[tid*4+1] + red[tid*4+2] + red[tid*4+3];
}

// ---------------- 5b) bias interpolation -> g_bias [bg][j][i] ----------------
__global__ void k_interp(){
    int idx = blockIdx.x*256 + threadIdx.x;    // 1048576 = bg*65536 + j*1024 + i
    int bg = idx>>16;
    int j  = (idx>>10)&63;
    int i  = idx&1023;
    float qx = 2.0f*(float)(i&31)*(1.0f/31.0f) - 1.0f;
    float qy = 2.0f*(float)(i>>5)*(1.0f/31.0f) - 1.0f;
    float2 kv = *(const float2*)&g_grid[(bg*JD+j)*2];
    float p0 = qx - kv.x, p1 = qy - kv.y;
    float f0 = copysignf(log1pf(fabsf(p0)), p0);
    float f1 = copysignf(log1pf(fabsf(p1)), p1);
    float u = fminf(fmaxf((f0+FMAXF)*TINV, 0.0f), 127.999f);
    float v = fminf(fmaxf((f1+FMAXF)*TINV, 0.0f), 127.999f);
    int iu=(int)u, iv=(int)v;
    float fu=u-(float)iu, fv=v-(float)iv;
    const float* t0 = g_tab + iv*TABN + iu;
    float a = t0[0]    + fu*(t0[1]-t0[0]);
    float b = t0[TABN] + fu*(t0[TABN+1]-t0[TABN]);
    g_bias[idx] = a + fv*(b-a);
}

// ---------------- 6) attention (bias now [bg][j][i], coalesced) ----------------
__global__ void k_attn(){
    __shared__ float ks[DH*JD];
    __shared__ float vs[DH*JD];
    int bg=blockIdx.y, it=blockIdx.x, tid=threadIdx.x;
    int b=bg>>3, g=bg&7;
    for(int i=tid;i<DH*JD;i+=128){ ks[i]=g_k[bg*DH*JD+i]; vs[i]=g_v[bg*DH*JD+i]; }
    __syncthreads();
    int i = it*128 + tid;
    const float* qp = g_q + (b*NC+g*DH)*HW + i;
    float sim[JD];
    #pragma unroll
    for(int j=0;j<JD;j++) sim[j]=0.f;
    for(int d=0;d<DH;d++){
        float qv = qp[d*HW];
        #pragma unroll
        for(int j=0;j<JD;j++) sim[j] += qv*ks[d*JD+j];
    }
    const float scale = 0.125f;
    const float* bp = g_bias + bg*JD*HW + i;
    float m=-1e30f;
    #pragma unroll
    for(int j=0;j<JD;j++){ sim[j] = sim[j]*scale + bp[j*HW]; m=fmaxf(m,sim[j]); }
    float ssum=0.f;
    #pragma unroll
    for(int j=0;j<JD;j++){ sim[j]=expf(sim[j]-m); ssum+=sim[j]; }
    float inv = 1.0f/ssum;
    float* op = g_attn + (b*NC+g*DH)*HW + i;
    for(int d=0;d<DH;d++){
        float a=0.f;
        #pragma unroll
        for(int j=0;j<JD;j++) a += sim[j]*vs[d*JD+j];
        op[d*HW] = a*inv;
    }
}

// ---------------- pipelined tf32 GEMM core ----------------
template<int MT, int KTOT>
__device__ __forceinline__ void gemm_core(const float* __restrict__ A,
                                          const float* __restrict__ Bb,
                                          int m0, int p0,
                                          float* As, float* Bs,
                                          float (*acc)[4][4]){
    constexpr int NA = MT*32/32;
    constexpr int NS = KTOT/32;
    int tid=threadIdx.x, lane=tid&31, wid=tid>>5;
    int g=lane>>2, t=lane&3;
    int mbase=(wid&1)*MT*16, nbase=(wid>>1)*32;
    float4 ra[NA], rb[4];
    #pragma unroll
    for(int ia=0; ia<NA; ia++){
        int idx = tid + ia*256;
        ra[ia] = *(const float4*)&A[(m0+(idx>>3))*KTOT + (idx&7)*4];
    }
    #pragma unroll
    for(int ib=0; ib<4; ib++){
        int idx = tid + ib*256;
        rb[ib] = *(const float4*)&Bb[(idx>>5)*HW + p0 + (idx&31)*4];
    }
    for(int s=0; s<NS; s++){
        if(s) __syncthreads();
        #pragma unroll
        for(int ia=0; ia<NA; ia++){
            int idx = tid + ia*256;
            float4 v = ra[ia];
            *(float4*)&As[(idx>>3)*36 + (idx&7)*4] =
                make_float4(tfr(v.x),tfr(v.y),tfr(v.z),tfr(v.w));
        }
        #pragma unroll
        for(int ib=0; ib<4; ib++){
            int idx = tid + ib*256;
            float4 v = rb[ib];
            *(float4*)&Bs[(idx>>5)*132 + (idx&31)*4] =
                make_float4(tfr(v.x),tfr(v.y),tfr(v.z),tfr(v.w));
        }
        __syncthreads();
        if(s+1<NS){
            int k0 = (s+1)*32;
            #pragma unroll
            for(int ia=0; ia<NA; ia++){
                int idx = tid + ia*256;
                ra[ia] = *(const float4*)&A[(m0+(idx>>3))*KTOT + k0 + (idx&7)*4];
            }
            #pragma unroll
            for(int ib=0; ib<4; ib++){
                int idx = tid + ib*256;
                rb[ib] = *(const float4*)&Bb[(k0+(idx>>5))*HW + p0 + (idx&31)*4];
            }
        }
        #pragma unroll
        for(int kc=0;kc<4;kc++){
            int K = kc*8;
            uint32_t af[MT][4];
            #pragma unroll
            for(int mt=0;mt<MT;mt++){
                const float* ap = As + (mbase+mt*16+g)*36 + K + t;
                af[mt][0] = __float_as_uint(ap[0]);
                af[mt][1] = __float_as_uint(ap[8*36]);
                af[mt][2] = __float_as_uint(ap[4]);
                af[mt][3] = __float_as_uint(ap[8*36+4]);
            }
            uint32_t bf[4][2];
            #pragma unroll
            for(int nt=0;nt<4;nt++){
                const float* bp = Bs + (K+t)*132 + nbase + nt*8 + g;
                bf[nt][0] = __float_as_uint(bp[0]);
                bf[nt][1] = __float_as_uint(bp[4*132]);
            }
            #pragma unroll
            for(int mt=0;mt<MT;mt++){
                #pragma unroll
                for(int nt=0;nt<4;nt++) mma_tf32(acc[mt][nt], af[mt], bf[nt]);
            }
        }
    }
}

// ---------------- 7) out projection + residual + fused bn2 ----------------
__global__ void __launch_bounds__(256,2) k_outproj(
        const float* __restrict__ ow, const float* __restrict__ ob,
        const float* __restrict__ x, const float* __restrict__ g2,
        const float* __restrict__ bb2){
    __shared__ float As[64*36];
    __shared__ float Bs[32*132];
    int m0 = blockIdx.y*64, n0 = blockIdx.x*128;
    int b = n0>>10, p0 = n0&1023;
    float acc[2][4][4];
    #pragma unroll
    for(int a=0;a<2;a++){ 
        #pragma unroll
        for(int nn=0;nn<4;nn++){ 
            #pragma unroll
            for(int cc=0;cc<4;cc++) acc[a][nn][cc]=0.f; } }
    gemm_core<2,512>(ow, g_attn + b*NC*HW, m0, p0, As, Bs, acc);
    int tid=threadIdx.x, lane=tid&31, wid=tid>>5;
    int g=lane>>2, t=lane&3;
    int mbase=(wid&1)*32, nbase=(wid>>1)*32;
    #pragma unroll
    for(int mt=0;mt<2;mt++){
        int mr = m0 + mbase + mt*16 + g;
        float bi0=ob[mr], bi1=ob[mr+8];
        float s0=g2[mr]*rsqrtf(1.0f+EPSBN), s1=g2[mr+8]*rsqrtf(1.0f+EPSBN);
        float c0=bb2[mr], c1=bb2[mr+8];
        #pragma unroll
        for(int nt=0;nt<4;nt++){
            int n = p0 + nbase + nt*8 + 2*t;
            int off0 = (b*NC + mr)*HW + n;
            int off1 = (b*NC + mr+8)*HW + n;
            float2 xv0 = *(const float2*)&x[off0];
            float2 xv1 = *(const float2*)&x[off1];
            float2 v0 = { xv0.x + acc[mt][nt][0] + bi0, xv0.y + acc[mt][nt][1] + bi0 };
            float2 v1 = { xv1.x + acc[mt][nt][2] + bi1, xv1.y + acc[mt][nt][3] + bi1 };
            *(float2*)&g_x2[off0] = v0;
            *(float2*)&g_x2[off1] = v1;
            float2 n0v = { v0.x*s0+c0, v0.y*s0+c0 };
            float2 n1v = { v1.x*s1+c1, v1.y*s1+c1 };
            *(float2*)&g_xn2[off0] = n0v;
            *(float2*)&g_xn2[off1] = n1v;
        }
    }
}

// ---------------- 8) MLP conv1 ----------------
__global__ void __launch_bounds__(256) k_mlp1(
        const float* __restrict__ w, const float* __restrict__ bias){
    __shared__ float As[128*36];
    __shared__ float Bs[32*132];
    int m0 = blockIdx.y*128, n0 = blockIdx.x*128;
    int b = n0>>10, p0 = n0&1023;
    float acc[4][4][4];
    #pragma unroll
    for(int a=0;a<4;a++){ 
        #pragma unroll
        for(int nn=0;nn<4;nn++){ 
            #pragma unroll
            for(int cc=0;cc<4;cc++) acc[a][nn][cc]=0.f; } }
    gemm_core<4,512>(w, g_xn2 + b*NC*HW, m0, p0, As, Bs, acc);
    int tid=threadIdx.x, lane=tid&31, wid=tid>>5;
    int g=lane>>2, t=lane&3;
    int mbase=(wid&1)*64, nbase=(wid>>1)*32;
    #pragma unroll
    for(int mt=0;mt<4;mt++){
        int mr = m0 + mbase + mt*16 + g;
        float bi0=bias[mr], bi1=bias[mr+8];
        #pragma unroll
        for(int nt=0;nt<4;nt++){
            int n = p0 + nbase + nt*8 + 2*t;
            float2 v0 = { gelu_exact(acc[mt][nt][0]+bi0), gelu_exact(acc[mt][nt][1]+bi0) };
            float2 v1 = { gelu_exact(acc[mt][nt][2]+bi1), gelu_exact(acc[mt][nt][3]+bi1) };
            *(float2*)&g_h1[(b*2048 + mr)*HW + n]   = v0;
            *(float2*)&g_h1[(b*2048 + mr+8)*HW + n] = v1;
        }
    }
}

// ---------------- 9) MLP conv2 + residual ----------------
__global__ void __launch_bounds__(256,2) k_mlp2(
        const float* __restrict__ w, const float* __restrict__ bias,
        float* __restrict__ out){
    __shared__ float As[64*36];
    __shared__ float Bs[32*132];
    int m0 = blockIdx.y*64, n0 = blockIdx.x*128;
    int b = n0>>10, p0 = n0&1023;
    float acc[2][4][4];
    #pragma unroll
    for(int a=0;a<2;a++){ 
        #pragma unroll
        for(int nn=0;nn<4;nn++){ 
            #pragma unroll
            for(int cc=0;cc<4;cc++) acc[a][nn][cc]=0.f; } }
    gemm_core<2,2048>(w, g_h1 + b*2048*HW, m0, p0, As, Bs, acc);
    int tid=threadIdx.x, lane=tid&31, wid=tid>>5;
    int g=lane>>2, t=lane&3;
    int mbase=(wid&1)*32, nbase=(wid>>1)*32;
    #pragma unroll
    for(int mt=0;mt<2;mt++){
        int mr = m0 + mbase + mt*16 + g;
        float bi0=bias[mr], bi1=bias[mr+8];
        #pragma unroll
        for(int nt=0;nt<4;nt++){
            int n = p0 + nbase + nt*8 + 2*t;
            int off0 = (b*NC + mr)*HW + n;
            int off1 = (b*NC + mr+8)*HW + n;
            float2 r0 = *(const float2*)&g_x2[off0];
            float2 r1 = *(const float2*)&g_x2[off1];
            float2 v0 = { r0.x + acc[mt][nt][0] + bi0, r0.y + acc[mt][nt][1] + bi0 };
            float2 v1 = { r1.x + acc[mt][nt][2] + bi1, r1.y + acc[mt][nt][3] + bi1 };
            *(float2*)&out[off0] = v0;
            *(float2*)&out[off1] = v1;
        }
    }
}

// ---------------- launch ----------------
extern "C" void kernel_launch(void* const* d_in, const int* in_sizes, int n_in,
                              void* d_out, int out_size){
    const float* x    = (const float*)d_in[0];
    const float* bn1g = (const float*)d_in[1];
    const float* bn1b = (const float*)d_in[2];
    const float* bn2g = (const float*)d_in[3];
    const float* bn2b = (const float*)d_in[4];
    const float* qw   = (const float*)d_in[5];
    const float* kw   = (const float*)d_in[6];
    const float* vw   = (const float*)d_in[7];
    const float* ow   = (const float*)d_in[8];
    const float* obv  = (const float*)d_in[9];
    const float* dw   = (const float*)d_in[10];
    const float* dwb  = (const float*)d_in[11];
    const float* pw   = (const float*)d_in[12];
    const float* cw1  = (const float*)d_in[13];
    const float* cb1  = (const float*)d_in[14];
    const float* cw2  = (const float*)d_in[15];
    const float* cb2  = (const float*)d_in[16];
    const float* cw3  = (const float*)d_in[17];
    const float* cb3  = (const float*)d_in[18];
    const float* mw1  = (const float*)d_in[19];
    const float* mb1  = (const float*)d_in[20];
    const float* mw2  = (const float*)d_in[21];
    const float* mb2  = (const float*)d_in[22];
    float* out = (float*)d_out;

    const int tab_smem = (256*132 + 128*132 + 1024 + 512 + 256 + 256 + 128) * 4;
    cudaFuncSetAttribute(k_tab, cudaFuncAttributeMaxDynamicSharedMemorySize, tab_smem);

    k_tab    <<<66,512,tab_smem>>>(cw1,cb1,cw2,cb2,cw3,cb3);   // independent of data path
    k_bn1    <<<4096,256>>>(x,bn1g,bn1b);
    k_qproj  <<<dim3(8,16),128>>>(qw);
    k_offsets<<<16,64>>>(dw,dwb,pw);
    k_sample <<<dim3(16,4),256>>>(kw,vw);
    k_interp <<<4096,256>>>();
    k_attn   <<<dim3(8,16),128>>>();
    k_outproj<<<dim3(16,8),256>>>(ow,obv,x,bn2g,bn2b);
    k_mlp1   <<<dim3(16,16),256>>>(mw1,mb1);
    k_mlp2   <<<dim3(16,8),256>>>(mw2,mb2,out);
}

// round 5
// speedup vs baseline: 6.6707x; 1.3645x over previous
#include <cuda_runtime.h>
#include <cstdint>

#define NB 2
#define NC 512
#define NH 32
#define NW 32
#define HW 1024
#define NG 8
#define DH 64
#define BG 16      // NB*NG
#define JD 64      // Hd*Wd = 8*8
#define EPSBN 1e-5f

// CPB feature-space table
#define TABN 129
#define FMAXF 1.43f
#define TSTEP (2.0f*FMAXF/128.0f)
#define TINV  (128.0f/(2.0f*FMAXF))

// ---------------- scratch ----------------
__device__ float g_xn[NB*NC*HW];
__device__ float g_q[NB*NC*HW];
__device__ float g_grid[BG*JD*2];
__device__ float g_k[BG*DH*JD];
__device__ float g_v[BG*DH*JD];
__device__ float g_bias[BG*HW*JD];   // layout [bg][j][i]
__device__ float g_attn[NB*NC*HW];
__device__ float g_x2[NB*NC*HW];
__device__ float g_xn2[NB*NC*HW];
__device__ float g_h1[NB*2048*HW];
__device__ float g_tab[TABN*TABN];

__device__ __forceinline__ float gelu_exact(float x){
    return 0.5f*x*(1.0f+erff(x*0.7071067811865476f));
}
__device__ __forceinline__ uint32_t f2tf(float v){
    uint32_t r; asm("cvt.rna.tf32.f32 %0, %1;" : "=r"(r) : "f"(v)); return r;
}
__device__ __forceinline__ float tfr(float v){ return __uint_as_float(f2tf(v)); }
__device__ __forceinline__ void mma_tf32(float c[4], const uint32_t a[4], const uint32_t b[2]){
    asm volatile("mma.sync.aligned.m16n8k8.row.col.f32.tf32.tf32.f32 "
        "{%0,%1,%2,%3}, {%4,%5,%6,%7}, {%8,%9}, {%0,%1,%2,%3};"
        : "+f"(c[0]),"+f"(c[1]),"+f"(c[2]),"+f"(c[3])
        : "r"(a[0]),"r"(a[1]),"r"(a[2]),"r"(a[3]),"r"(b[0]),"r"(b[1]));
}

// ---------------- 1) bn1 ----------------
__global__ void k_bn1(const float* __restrict__ x, const float* __restrict__ g1,
                      const float* __restrict__ b1){
    int idx = blockIdx.x*256 + threadIdx.x;
    int c = (idx>>10)&(NC-1);
    float s = g1[c]*rsqrtf(1.0f+EPSBN);
    g_xn[idx] = x[idx]*s + b1[c];
}

// ---------------- 2) q grouped 1x1 conv ----------------
__global__ void k_qproj(const float* __restrict__ qw){
    __shared__ float ws[DH*DH];
    __shared__ float xs[DH*128];
    int bg = blockIdx.y; int b = bg>>3, g = bg&7;
    int p0 = blockIdx.x*128;
    int tid = threadIdx.x;
    const float* wsrc = qw + g*DH*DH;
    for(int i=tid;i<DH*DH;i+=128) ws[i]=wsrc[i];
    const float* xsrc = g_xn + (b*NC + g*DH)*HW + p0;
    for(int i=tid;i<DH*128;i+=128){ int c=i>>7, col=i&127; xs[c*128+col]=xsrc[c*HW+col]; }
    __syncthreads();
    float acc[DH];
    #pragma unroll
    for(int o=0;o<DH;o++) acc[o]=0.f;
    for(int c=0;c<DH;c++){
        float xv = xs[c*128+tid];
        #pragma unroll
        for(int o=0;o<DH;o++) acc[o] += ws[o*DH+c]*xv;
    }
    float* qdst = g_q + (b*NC + g*DH)*HW + p0 + tid;
    #pragma unroll
    for(int o=0;o<DH;o++) qdst[o*HW]=acc[o];
}

// ---------------- 3) offsets: one warp per (bg, output position) ----------------
// 1024 warps = 16 bg x 64 positions; lanes split 64 channels (2 each).
__global__ void __launch_bounds__(256) k_offsets(
        const float* __restrict__ dw, const float* __restrict__ dwb,
        const float* __restrict__ pw){
    __shared__ float dws[DH*36];
    int tid = threadIdx.x;
    for(int i=tid;i<DH*36;i+=256) dws[i]=dw[i];
    __syncthreads();
    int gw = blockIdx.x*8 + (tid>>5);     // 0..1023
    int bg = gw>>6, pos = gw&63;
    int lane = tid&31;
    int b=bg>>3, g=bg&7;
    int oy=pos>>3, ox=pos&7;
    const float* qp = g_q + (b*NC+g*DH)*HW;
    float a0=0.f, a1=0.f;
    #pragma unroll
    for(int cc=0; cc<2; cc++){
        int ch = lane + cc*32;
        const float* qc = qp + ch*HW;
        const float* wv = dws + ch*36;
        float s=0.f;
        #pragma unroll
        for(int ky=0;ky<6;ky++){
            int iy = oy*4-1+ky;
            if(iy<0||iy>=NH) continue;
            #pragma unroll
            for(int kx=0;kx<6;kx++){
                int ix = ox*4-1+kx;
                if(ix<0||ix>=NW) continue;
                s += qc[iy*NW+ix]*wv[ky*6+kx];
            }
        }
        s = gelu_exact(s + dwb[ch]);
        a0 += s*pw[ch];
        a1 += s*pw[DH+ch];
    }
    #pragma unroll
    for(int o=16;o>0;o>>=1){
        a0 += __shfl_xor_sync(0xffffffffu, a0, o);
        a1 += __shfl_xor_sync(0xffffffffu, a1, o);
    }
    if(lane==0){
        float vx = (float)ox + tanhf(a0)*4.0f;
        float vy = (float)oy + tanhf(a1)*4.0f;
        g_grid[(bg*JD+pos)*2+0] = 2.0f*vx/7.0f - 1.0f;
        g_grid[(bg*JD+pos)*2+1] = 2.0f*vy/7.0f - 1.0f;
    }
}

// ---------------- 4) grid_sample + k/v grouped conv ----------------
__global__ void k_sample(const float* __restrict__ kw, const float* __restrict__ vw){
    __shared__ float kvs[DH*JD];
    __shared__ float kws[DH*DH];
    __shared__ float vws[DH*DH];
    int bg=blockIdx.x, gy=blockIdx.y, tid=threadIdx.x;
    int b=bg>>3, g=bg&7;
    for(int i=tid;i<DH*DH;i+=256){ kws[i]=kw[g*DH*DH+i]; vws[i]=vw[g*DH*DH+i]; }
    const float* img = g_xn + (b*NC+g*DH)*HW;
    for(int i=tid;i<DH*JD;i+=256){
        int c=i>>6, j=i&63;
        float nx=g_grid[(bg*JD+j)*2], ny=g_grid[(bg*JD+j)*2+1];
        float gx=(nx+1.0f)*16.0f-0.5f;
        float gy2=(ny+1.0f)*16.0f-0.5f;
        float x0f=floorf(gx), y0f=floorf(gy2);
        float wx=gx-x0f, wy=gy2-y0f;
        int x0=(int)x0f, y0=(int)y0f;
        const float* im=img+c*HW;
        float v00=0.f,v01=0.f,v10=0.f,v11=0.f;
        bool xi0 = (x0>=0)&&(x0<NW), xi1 = (x0+1>=0)&&(x0+1<NW);
        bool yi0 = (y0>=0)&&(y0<NH), yi1 = (y0+1>=0)&&(y0+1<NH);
        if(yi0){ if(xi0) v00=im[y0*NW+x0]; if(xi1) v01=im[y0*NW+x0+1]; }
        if(yi1){ if(xi0) v10=im[(y0+1)*NW+x0]; if(xi1) v11=im[(y0+1)*NW+x0+1]; }
        kvs[c*JD+j] = v00*(1.f-wx)*(1.f-wy)+v01*wx*(1.f-wy)+v10*(1.f-wx)*wy+v11*wx*wy;
    }
    __syncthreads();
    for(int i=tid;i<16*JD;i+=256){
        int o=gy*16 + (i>>6), j=i&63;
        float ka=0.f,va=0.f;
        for(int c=0;c<DH;c++){
            float kvv=kvs[c*JD+j];
            ka += kws[o*DH+c]*kvv;
            va += vws[o*DH+c]*kvv;
        }
        g_k[bg*DH*JD + o*JD + j] = ka;
        g_v[bg*DH*JD + o*JD + j] = va;
    }
}

// ---------------- 5a) CPB table on 129x129 feature grid (mma) ----------------
__global__ void __launch_bounds__(512,1) k_tab(
        const float* __restrict__ w1, const float* __restrict__ b1,
        const float* __restrict__ w2, const float* __restrict__ b2,
        const float* __restrict__ w3, const float* __restrict__ b3){
    extern __shared__ float sm[];
    float* Hs  = sm;
    float* Ws  = Hs + 256*132;
    float* red = Ws + 128*132;
    float* f0s = red + 1024;
    float* f1s = f0s + 256;
    float* b2s = f1s + 256;
    float* w3s = b2s + 128;
    float* w1s = w3s + 128;
    float* b1s = w1s + 256;
    int tid = threadIdx.x;
    int pt0 = blockIdx.x*256;
    if(tid<256){
        int pt = pt0 + tid;
        int v = pt/TABN;
        int u = pt - v*TABN;
        f0s[tid] = -FMAXF + (float)u*TSTEP;
        f1s[tid] = -FMAXF + (float)v*TSTEP;
        w1s[tid] = w1[tid];
    }
    if(tid<128){ b1s[tid]=b1[tid]; b2s[tid]=b2[tid]; w3s[tid]=w3[tid]; }
    #pragma unroll
    for(int it=0; it<8; it++){
        int idx = tid + it*512;
        int k = idx>>5, n4 = (idx&31)*4;
        float4 v = *(const float4*)&w2[k*128 + n4];
        *(float4*)&Ws[k*132 + n4] = make_float4(tfr(v.x),tfr(v.y),tfr(v.z),tfr(v.w));
    }
    __syncthreads();
    #pragma unroll
    for(int it=0; it<16; it++){
        int idx = tid + it*512;
        int m = idx>>5, k4 = (idx&31)*4;
        float f0 = f0s[m], f1 = f1s[m];
        float4 wv0 = *(const float4*)&w1s[k4];
        float4 wv1 = *(const float4*)&w1s[128+k4];
        float4 bv  = *(const float4*)&b1s[k4];
        float4 h;
        h.x = tfr(fmaxf(f0*wv0.x + f1*wv1.x + bv.x, 0.f));
        h.y = tfr(fmaxf(f0*wv0.y + f1*wv1.y + bv.y, 0.f));
        h.z = tfr(fmaxf(f0*wv0.z + f1*wv1.z + bv.z, 0.f));
        h.w = tfr(fmaxf(f0*wv0.w + f1*wv1.w + bv.w, 0.f));
        *(float4*)&Hs[m*132 + k4] = h;
    }
    __syncthreads();

    int lane = tid&31, wid = tid>>5;
    int g = lane>>2, t = lane&3;
    int mbase = (wid&3)*64, nbase = (wid>>2)*32;
    float acc[4][4][4];
    #pragma unroll
    for(int a=0;a<4;a++){
        #pragma unroll
        for(int nn=0;nn<4;nn++){
            #pragma unroll
            for(int cc=0;cc<4;cc++) acc[a][nn][cc]=0.f; } }

    #pragma unroll 4
    for(int kc=0;kc<16;kc++){
        int K = kc*8;
        uint32_t af[4][4];
        #pragma unroll
        for(int mt=0;mt<4;mt++){
            const float* ap = Hs + (mbase+mt*16+g)*132 + K + t;
            af[mt][0] = __float_as_uint(ap[0]);
            af[mt][1] = __float_as_uint(ap[8*132]);
            af[mt][2] = __float_as_uint(ap[4]);
            af[mt][3] = __float_as_uint(ap[8*132+4]);
        }
        uint32_t bf[4][2];
        #pragma unroll
        for(int nt=0;nt<4;nt++){
            const float* bp = Ws + (K+t)*132 + nbase + nt*8 + g;
            bf[nt][0] = __float_as_uint(bp[0]);
            bf[nt][1] = __float_as_uint(bp[4*132]);
        }
        #pragma unroll
        for(int mt=0;mt<4;mt++){
            #pragma unroll
            for(int nt=0;nt<4;nt++) mma_tf32(acc[mt][nt], af[mt], bf[nt]);
        }
    }
    #pragma unroll
    for(int mt=0;mt<4;mt++){
        float pA=0.f, pB=0.f;
        #pragma unroll
        for(int nt=0;nt<4;nt++){
            int n = nbase + nt*8 + 2*t;
            float ba=b2s[n], bb=b2s[n+1], wa=w3s[n], wb=w3s[n+1];
            pA += fmaxf(acc[mt][nt][0]+ba,0.f)*wa + fmaxf(acc[mt][nt][1]+bb,0.f)*wb;
            pB += fmaxf(acc[mt][nt][2]+ba,0.f)*wa + fmaxf(acc[mt][nt][3]+bb,0.f)*wb;
        }
        pA += __shfl_xor_sync(0xffffffffu, pA, 1);
        pA += __shfl_xor_sync(0xffffffffu, pA, 2);
        pB += __shfl_xor_sync(0xffffffffu, pB, 1);
        pB += __shfl_xor_sync(0xffffffffu, pB, 2);
        if(t==0){
            int rA = mbase+mt*16+g;
            red[rA*4 + (wid>>2)]     = pA;
            red[(rA+8)*4 + (wid>>2)] = pB;
        }
    }
    __syncthreads();
    if(tid<256 && pt0+tid<TABN*TABN)
        g_tab[pt0+tid] = b3[0] + red[tid*4] + red[tid*4+1] + red[tid*4+2] + red[tid*4+3];
}

// ---------------- 5b) bias interpolation -> g_bias [bg][j][i] ----------------
__global__ void k_interp(){
    int idx = blockIdx.x*256 + threadIdx.x;
    int bg = idx>>16;
    int j  = (idx>>10)&63;
    int i  = idx&1023;
    float qx = 2.0f*(float)(i&31)*(1.0f/31.0f) - 1.0f;
    float qy = 2.0f*(float)(i>>5)*(1.0f/31.0f) - 1.0f;
    float2 kv = *(const float2*)&g_grid[(bg*JD+j)*2];
    float p0 = qx - kv.x, p1 = qy - kv.y;
    float f0 = copysignf(log1pf(fabsf(p0)), p0);
    float f1 = copysignf(log1pf(fabsf(p1)), p1);
    float u = fminf(fmaxf((f0+FMAXF)*TINV, 0.0f), 127.999f);
    float v = fminf(fmaxf((f1+FMAXF)*TINV, 0.0f), 127.999f);
    int iu=(int)u, iv=(int)v;
    float fu=u-(float)iu, fv=v-(float)iv;
    const float* t0 = g_tab + iv*TABN + iu;
    float a = t0[0]    + fu*(t0[1]-t0[0]);
    float b = t0[TABN] + fu*(t0[TABN+1]-t0[TABN]);
    g_bias[idx] = a + fv*(b-a);
}

// ---------------- 6) attention ----------------
__global__ void k_attn(){
    __shared__ float ks[DH*JD];
    __shared__ float vs[DH*JD];
    int bg=blockIdx.y, it=blockIdx.x, tid=threadIdx.x;
    int b=bg>>3, g=bg&7;
    for(int i=tid;i<DH*JD;i+=128){ ks[i]=g_k[bg*DH*JD+i]; vs[i]=g_v[bg*DH*JD+i]; }
    __syncthreads();
    int i = it*128 + tid;
    const float* qp = g_q + (b*NC+g*DH)*HW + i;
    float sim[JD];
    #pragma unroll
    for(int j=0;j<JD;j++) sim[j]=0.f;
    for(int d=0;d<DH;d++){
        float qv = qp[d*HW];
        #pragma unroll
        for(int j=0;j<JD;j++) sim[j] += qv*ks[d*JD+j];
    }
    const float scale = 0.125f;
    const float* bp = g_bias + bg*JD*HW + i;
    float m=-1e30f;
    #pragma unroll
    for(int j=0;j<JD;j++){ sim[j] = sim[j]*scale + bp[j*HW]; m=fmaxf(m,sim[j]); }
    float ssum=0.f;
    #pragma unroll
    for(int j=0;j<JD;j++){ sim[j]=expf(sim[j]-m); ssum+=sim[j]; }
    float inv = 1.0f/ssum;
    float* op = g_attn + (b*NC+g*DH)*HW + i;
    for(int d=0;d<DH;d++){
        float a=0.f;
        #pragma unroll
        for(int j=0;j<JD;j++) a += sim[j]*vs[d*JD+j];
        op[d*HW] = a*inv;
    }
}

// ---------------- pipelined tf32 GEMM core ----------------
template<int MT, int KTOT>
__device__ __forceinline__ void gemm_core(const float* __restrict__ A,
                                          const float* __restrict__ Bb,
                                          int m0, int p0,
                                          float* As, float* Bs,
                                          float (*acc)[4][4]){
    constexpr int NA = MT*32/32;
    constexpr int NS = KTOT/32;
    int tid=threadIdx.x, lane=tid&31, wid=tid>>5;
    int g=lane>>2, t=lane&3;
    int mbase=(wid&1)*MT*16, nbase=(wid>>1)*32;
    float4 ra[NA], rb[4];
    #pragma unroll
    for(int ia=0; ia<NA; ia++){
        int idx = tid + ia*256;
        ra[ia] = *(const float4*)&A[(m0+(idx>>3))*KTOT + (idx&7)*4];
    }
    #pragma unroll
    for(int ib=0; ib<4; ib++){
        int idx = tid + ib*256;
        rb[ib] = *(const float4*)&Bb[(idx>>5)*HW + p0 + (idx&31)*4];
    }
    for(int s=0; s<NS; s++){
        if(s) __syncthreads();
        #pragma unroll
        for(int ia=0; ia<NA; ia++){
            int idx = tid + ia*256;
            float4 v = ra[ia];
            *(float4*)&As[(idx>>3)*36 + (idx&7)*4] =
                make_float4(tfr(v.x),tfr(v.y),tfr(v.z),tfr(v.w));
        }
        #pragma unroll
        for(int ib=0; ib<4; ib++){
            int idx = tid + ib*256;
            float4 v = rb[ib];
            *(float4*)&Bs[(idx>>5)*132 + (idx&31)*4] =
                make_float4(tfr(v.x),tfr(v.y),tfr(v.z),tfr(v.w));
        }
        __syncthreads();
        if(s+1<NS){
            int k0 = (s+1)*32;
            #pragma unroll
            for(int ia=0; ia<NA; ia++){
                int idx = tid + ia*256;
                ra[ia] = *(const float4*)&A[(m0+(idx>>3))*KTOT + k0 + (idx&7)*4];
            }
            #pragma unroll
            for(int ib=0; ib<4; ib++){
                int idx = tid + ib*256;
                rb[ib] = *(const float4*)&Bb[(k0+(idx>>5))*HW + p0 + (idx&31)*4];
            }
        }
        #pragma unroll
        for(int kc=0;kc<4;kc++){
            int K = kc*8;
            uint32_t af[MT][4];
            #pragma unroll
            for(int mt=0;mt<MT;mt++){
                const float* ap = As + (mbase+mt*16+g)*36 + K + t;
                af[mt][0] = __float_as_uint(ap[0]);
                af[mt][1] = __float_as_uint(ap[8*36]);
                af[mt][2] = __float_as_uint(ap[4]);
                af[mt][3] = __float_as_uint(ap[8*36+4]);
            }
            uint32_t bf[4][2];
            #pragma unroll
            for(int nt=0;nt<4;nt++){
                const float* bp = Bs + (K+t)*132 + nbase + nt*8 + g;
                bf[nt][0] = __float_as_uint(bp[0]);
                bf[nt][1] = __float_as_uint(bp[4*132]);
            }
            #pragma unroll
            for(int mt=0;mt<MT;mt++){
                #pragma unroll
                for(int nt=0;nt<4;nt++) mma_tf32(acc[mt][nt], af[mt], bf[nt]);
            }
        }
    }
}

// ---------------- 7) out projection + residual + fused bn2 ----------------
__global__ void __launch_bounds__(256,2) k_outproj(
        const float* __restrict__ ow, const float* __restrict__ ob,
        const float* __restrict__ x, const float* __restrict__ g2,
        const float* __restrict__ bb2){
    __shared__ float As[64*36];
    __shared__ float Bs[32*132];
    int m0 = blockIdx.y*64, n0 = blockIdx.x*128;
    int b = n0>>10, p0 = n0&1023;
    float acc[2][4][4];
    #pragma unroll
    for(int a=0;a<2;a++){ 
        #pragma unroll
        for(int nn=0;nn<4;nn++){ 
            #pragma unroll
            for(int cc=0;cc<4;cc++) acc[a][nn][cc]=0.f; } }
    gemm_core<2,512>(ow, g_attn + b*NC*HW, m0, p0, As, Bs, acc);
    int tid=threadIdx.x, lane=tid&31, wid=tid>>5;
    int g=lane>>2, t=lane&3;
    int mbase=(wid&1)*32, nbase=(wid>>1)*32;
    #pragma unroll
    for(int mt=0;mt<2;mt++){
        int mr = m0 + mbase + mt*16 + g;
        float bi0=ob[mr], bi1=ob[mr+8];
        float s0=g2[mr]*rsqrtf(1.0f+EPSBN), s1=g2[mr+8]*rsqrtf(1.0f+EPSBN);
        float c0=bb2[mr], c1=bb2[mr+8];
        #pragma unroll
        for(int nt=0;nt<4;nt++){
            int n = p0 + nbase + nt*8 + 2*t;
            int off0 = (b*NC + mr)*HW + n;
            int off1 = (b*NC + mr+8)*HW + n;
            float2 xv0 = *(const float2*)&x[off0];
            float2 xv1 = *(const float2*)&x[off1];
            float2 v0 = { xv0.x + acc[mt][nt][0] + bi0, xv0.y + acc[mt][nt][1] + bi0 };
            float2 v1 = { xv1.x + acc[mt][nt][2] + bi1, xv1.y + acc[mt][nt][3] + bi1 };
            *(float2*)&g_x2[off0] = v0;
            *(float2*)&g_x2[off1] = v1;
            float2 n0v = { v0.x*s0+c0, v0.y*s0+c0 };
            float2 n1v = { v1.x*s1+c1, v1.y*s1+c1 };
            *(float2*)&g_xn2[off0] = n0v;
            *(float2*)&g_xn2[off1] = n1v;
        }
    }
}

// ---------------- 8) MLP conv1 ----------------
__global__ void __launch_bounds__(256) k_mlp1(
        const float* __restrict__ w, const float* __restrict__ bias){
    __shared__ float As[128*36];
    __shared__ float Bs[32*132];
    int m0 = blockIdx.y*128, n0 = blockIdx.x*128;
    int b = n0>>10, p0 = n0&1023;
    float acc[4][4][4];
    #pragma unroll
    for(int a=0;a<4;a++){ 
        #pragma unroll
        for(int nn=0;nn<4;nn++){ 
            #pragma unroll
            for(int cc=0;cc<4;cc++) acc[a][nn][cc]=0.f; } }
    gemm_core<4,512>(w, g_xn2 + b*NC*HW, m0, p0, As, Bs, acc);
    int tid=threadIdx.x, lane=tid&31, wid=tid>>5;
    int g=lane>>2, t=lane&3;
    int mbase=(wid&1)*64, nbase=(wid>>1)*32;
    #pragma unroll
    for(int mt=0;mt<4;mt++){
        int mr = m0 + mbase + mt*16 + g;
        float bi0=bias[mr], bi1=bias[mr+8];
        #pragma unroll
        for(int nt=0;nt<4;nt++){
            int n = p0 + nbase + nt*8 + 2*t;
            float2 v0 = { gelu_exact(acc[mt][nt][0]+bi0), gelu_exact(acc[mt][nt][1]+bi0) };
            float2 v1 = { gelu_exact(acc[mt][nt][2]+bi1), gelu_exact(acc[mt][nt][3]+bi1) };
            *(float2*)&g_h1[(b*2048 + mr)*HW + n]   = v0;
            *(float2*)&g_h1[(b*2048 + mr+8)*HW + n] = v1;
        }
    }
}

// ---------------- 9) MLP conv2 + residual ----------------
__global__ void __launch_bounds__(256,2) k_mlp2(
        const float* __restrict__ w, const float* __restrict__ bias,
        float* __restrict__ out){
    __shared__ float As[64*36];
    __shared__ float Bs[32*132];
    int m0 = blockIdx.y*64, n0 = blockIdx.x*128;
    int b = n0>>10, p0 = n0&1023;
    float acc[2][4][4];
    #pragma unroll
    for(int a=0;a<2;a++){ 
        #pragma unroll
        for(int nn=0;nn<4;nn++){ 
            #pragma unroll
            for(int cc=0;cc<4;cc++) acc[a][nn][cc]=0.f; } }
    gemm_core<2,2048>(w, g_h1 + b*2048*HW, m0, p0, As, Bs, acc);
    int tid=threadIdx.x, lane=tid&31, wid=tid>>5;
    int g=lane>>2, t=lane&3;
    int mbase=(wid&1)*32, nbase=(wid>>1)*32;
    #pragma unroll
    for(int mt=0;mt<2;mt++){
        int mr = m0 + mbase + mt*16 + g;
        float bi0=bias[mr], bi1=bias[mr+8];
        #pragma unroll
        for(int nt=0;nt<4;nt++){
            int n = p0 + nbase + nt*8 + 2*t;
            int off0 = (b*NC + mr)*HW + n;
            int off1 = (b*NC + mr+8)*HW + n;
            float2 r0 = *(const float2*)&g_x2[off0];
            float2 r1 = *(const float2*)&g_x2[off1];
            float2 v0 = { r0.x + acc[mt][nt][0] + bi0, r0.y + acc[mt][nt][1] + bi0 };
            float2 v1 = { r1.x + acc[mt][nt][2] + bi1, r1.y + acc[mt][nt][3] + bi1 };
            *(float2*)&out[off0] = v0;
            *(float2*)&out[off1] = v1;
        }
    }
}

// ---------------- launch ----------------
extern "C" void kernel_launch(void* const* d_in, const int* in_sizes, int n_in,
                              void* d_out, int out_size){
    const float* x    = (const float*)d_in[0];
    const float* bn1g = (const float*)d_in[1];
    const float* bn1b = (const float*)d_in[2];
    const float* bn2g = (const float*)d_in[3];
    const float* bn2b = (const float*)d_in[4];
    const float* qw   = (const float*)d_in[5];
    const float* kw   = (const float*)d_in[6];
    const float* vw   = (const float*)d_in[7];
    const float* ow   = (const float*)d_in[8];
    const float* obv  = (const float*)d_in[9];
    const float* dw   = (const float*)d_in[10];
    const float* dwb  = (const float*)d_in[11];
    const float* pw   = (const float*)d_in[12];
    const float* cw1  = (const float*)d_in[13];
    const float* cb1  = (const float*)d_in[14];
    const float* cw2  = (const float*)d_in[15];
    const float* cb2  = (const float*)d_in[16];
    const float* cw3  = (const float*)d_in[17];
    const float* cb3  = (const float*)d_in[18];
    const float* mw1  = (const float*)d_in[19];
    const float* mb1  = (const float*)d_in[20];
    const float* mw2  = (const float*)d_in[21];
    const float* mb2  = (const float*)d_in[22];
    float* out = (float*)d_out;

    const int tab_smem = (256*132 + 128*132 + 1024 + 512 + 256 + 256 + 128) * 4;
    cudaFuncSetAttribute(k_tab, cudaFuncAttributeMaxDynamicSharedMemorySize, tab_smem);

    k_tab    <<<66,512,tab_smem>>>(cw1,cb1,cw2,cb2,cw3,cb3);
    k_bn1    <<<4096,256>>>(x,bn1g,bn1b);
    k_qproj  <<<dim3(8,16),128>>>(qw);
    k_offsets<<<128,256>>>(dw,dwb,pw);
    k_sample <<<dim3(16,4),256>>>(kw,vw);
    k_interp <<<4096,256>>>();
    k_attn   <<<dim3(8,16),128>>>();
    k_outproj<<<dim3(16,8),256>>>(ow,obv,x,bn2g,bn2b);
    k_mlp1   <<<dim3(16,16),256>>>(mw1,mb1);
    k_mlp2   <<<dim3(16,8),256>>>(mw2,mb2,out);
}

// round 6
// speedup vs baseline: 7.8579x; 1.1780x over previous
#include <cuda_runtime.h>
#include <cstdint>

#define NB 2
#define NC 512
#define NH 32
#define NW 32
#define HW 1024
#define NG 8
#define DH 64
#define BG 16
#define JD 64
#define EPSBN 1e-5f

#define TABN 129
#define FMAXF 1.43f
#define TSTEP (2.0f*FMAXF/128.0f)
#define TINV  (128.0f/(2.0f*FMAXF))

// ---------------- scratch ----------------
__device__ float g_xn[NB*NC*HW];
__device__ float g_q[NB*NC*HW];
__device__ float g_grid[BG*JD*2];
__device__ float g_k[BG*DH*JD];
__device__ float g_v[BG*DH*JD];
__device__ float g_bias[BG*HW*JD];   // [bg][j][i]
__device__ float g_attn[NB*NC*HW];
__device__ float g_x2[NB*NC*HW];
__device__ float g_xn2[NB*NC*HW];
__device__ float g_h1[NB*2048*HW];
__device__ float g_tab[TABN*TABN];

__device__ __forceinline__ float gelu_exact(float x){
    return 0.5f*x*(1.0f+erff(x*0.7071067811865476f));
}
__device__ __forceinline__ uint32_t f2tf(float v){
    uint32_t r; asm("cvt.rna.tf32.f32 %0, %1;" : "=r"(r) : "f"(v)); return r;
}
__device__ __forceinline__ float tfr(float v){ return __uint_as_float(f2tf(v)); }
__device__ __forceinline__ void mma_tf32(float c[4], const uint32_t a[4], const uint32_t b[2]){
    asm volatile("mma.sync.aligned.m16n8k8.row.col.f32.tf32.tf32.f32 "
        "{%0,%1,%2,%3}, {%4,%5,%6,%7}, {%8,%9}, {%0,%1,%2,%3};"
        : "+f"(c[0]),"+f"(c[1]),"+f"(c[2]),"+f"(c[3])
        : "r"(a[0]),"r"(a[1]),"r"(a[2]),"r"(a[3]),"r"(b[0]),"r"(b[1]));
}
__device__ __forceinline__ void cpa16(float* smem, const float* gmem){
    uint32_t s = (uint32_t)__cvta_generic_to_shared(smem);
    asm volatile("cp.async.ca.shared.global [%0], [%1], 16;" :: "r"(s), "l"(gmem));
}

// ---------------- 1) bn1 (float4) ----------------
__global__ void k_bn1(const float* __restrict__ x, const float* __restrict__ g1,
                      const float* __restrict__ b1){
    int idx4 = blockIdx.x*256 + threadIdx.x;          // 262144
    int c = (idx4>>8)&(NC-1);
    float s = g1[c]*rsqrtf(1.0f+EPSBN);
    float bb = b1[c];
    float4 v = *(const float4*)&x[idx4*4];
    float4 o = { v.x*s+bb, v.y*s+bb, v.z*s+bb, v.w*s+bb };
    *(float4*)&g_xn[idx4*4] = o;
}

// ---------------- 2) q grouped 1x1 conv ----------------
__global__ void k_qproj(const float* __restrict__ qw){
    __shared__ float ws[DH*DH];
    __shared__ float xs[DH*128];
    int bg = blockIdx.y; int b = bg>>3, g = bg&7;
    int p0 = blockIdx.x*128;
    int tid = threadIdx.x;
    const float* wsrc = qw + g*DH*DH;
    for(int i=tid;i<DH*DH;i+=128) ws[i]=wsrc[i];
    const float* xsrc = g_xn + (b*NC + g*DH)*HW + p0;
    for(int i=tid;i<DH*128;i+=128){ int c=i>>7, col=i&127; xs[c*128+col]=xsrc[c*HW+col]; }
    __syncthreads();
    float acc[DH];
    #pragma unroll
    for(int o=0;o<DH;o++) acc[o]=0.f;
    for(int c=0;c<DH;c++){
        float xv = xs[c*128+tid];
        #pragma unroll
        for(int o=0;o<DH;o++) acc[o] += ws[o*DH+c]*xv;
    }
    float* qdst = g_q + (b*NC + g*DH)*HW + p0 + tid;
    #pragma unroll
    for(int o=0;o<DH;o++) qdst[o*HW]=acc[o];
}

// ---------------- 3) offsets: one warp per (bg, position) ----------------
__global__ void __launch_bounds__(256) k_offsets(
        const float* __restrict__ dw, const float* __restrict__ dwb,
        const float* __restrict__ pw){
    __shared__ float dws[DH*36];
    int tid = threadIdx.x;
    for(int i=tid;i<DH*36;i+=256) dws[i]=dw[i];
    __syncthreads();
    int gw = blockIdx.x*8 + (tid>>5);
    int bg = gw>>6, pos = gw&63;
    int lane = tid&31;
    int b=bg>>3, g=bg&7;
    int oy=pos>>3, ox=pos&7;
    const float* qp = g_q + (b*NC+g*DH)*HW;
    float a0=0.f, a1=0.f;
    #pragma unroll
    for(int cc=0; cc<2; cc++){
        int ch = lane + cc*32;
        const float* qc = qp + ch*HW;
        const float* wv = dws + ch*36;
        float s=0.f;
        #pragma unroll
        for(int ky=0;ky<6;ky++){
            int iy = oy*4-1+ky;
            if(iy<0||iy>=NH) continue;
            #pragma unroll
            for(int kx=0;kx<6;kx++){
                int ix = ox*4-1+kx;
                if(ix<0||ix>=NW) continue;
                s += qc[iy*NW+ix]*wv[ky*6+kx];
            }
        }
        s = gelu_exact(s + dwb[ch]);
        a0 += s*pw[ch];
        a1 += s*pw[DH+ch];
    }
    #pragma unroll
    for(int o=16;o>0;o>>=1){
        a0 += __shfl_xor_sync(0xffffffffu, a0, o);
        a1 += __shfl_xor_sync(0xffffffffu, a1, o);
    }
    if(lane==0){
        float vx = (float)ox + tanhf(a0)*4.0f;
        float vy = (float)oy + tanhf(a1)*4.0f;
        g_grid[(bg*JD+pos)*2+0] = 2.0f*vx/7.0f - 1.0f;
        g_grid[(bg*JD+pos)*2+1] = 2.0f*vy/7.0f - 1.0f;
    }
}

// ---------------- 4) grid_sample + k/v conv, block = (bg, 16-j chunk) ----------------
__global__ void k_sample(const float* __restrict__ kw, const float* __restrict__ vw){
    __shared__ float kvs[DH*16];
    __shared__ float kws[DH*DH];
    __shared__ float vws[DH*DH];
    int bg=blockIdx.x, jq=blockIdx.y, tid=threadIdx.x;   // 256 threads
    int b=bg>>3, g=bg&7;
    for(int i=tid;i<DH*DH;i+=256){ kws[i]=kw[g*DH*DH+i]; vws[i]=vw[g*DH*DH+i]; }
    const float* img = g_xn + (b*NC+g*DH)*HW;
    for(int i=tid;i<DH*16;i+=256){
        int c=i>>4, jl=i&15, j=jq*16+jl;
        float nx=g_grid[(bg*JD+j)*2], ny=g_grid[(bg*JD+j)*2+1];
        float gx=(nx+1.0f)*16.0f-0.5f;
        float gy2=(ny+1.0f)*16.0f-0.5f;
        float x0f=floorf(gx), y0f=floorf(gy2);
        float wx=gx-x0f, wy=gy2-y0f;
        int x0=(int)x0f, y0=(int)y0f;
        const float* im=img+c*HW;
        float v00=0.f,v01=0.f,v10=0.f,v11=0.f;
        bool xi0 = (x0>=0)&&(x0<NW), xi1 = (x0+1>=0)&&(x0+1<NW);
        bool yi0 = (y0>=0)&&(y0<NH), yi1 = (y0+1>=0)&&(y0+1<NH);
        if(yi0){ if(xi0) v00=im[y0*NW+x0]; if(xi1) v01=im[y0*NW+x0+1]; }
        if(yi1){ if(xi0) v10=im[(y0+1)*NW+x0]; if(xi1) v11=im[(y0+1)*NW+x0+1]; }
        kvs[c*16+jl] = v00*(1.f-wx)*(1.f-wy)+v01*wx*(1.f-wy)+v10*(1.f-wx)*wy+v11*wx*wy;
    }
    __syncthreads();
    for(int i=tid;i<DH*16;i+=256){
        int o=i>>4, jl=i&15, j=jq*16+jl;
        float ka=0.f,va=0.f;
        for(int c=0;c<DH;c++){
            float kvv=kvs[c*16+jl];
            ka += kws[o*DH+c]*kvv;
            va += vws[o*DH+c]*kvv;
        }
        g_k[bg*DH*JD + o*JD + j] = ka;
        g_v[bg*DH*JD + o*JD + j] = va;
    }
}

// ---------------- 5a) CPB table on 129x129 feature grid (mma) ----------------
__global__ void __launch_bounds__(512,1) k_tab(
        const float* __restrict__ w1, const float* __restrict__ b1,
        const float* __restrict__ w2, const float* __restrict__ b2,
        const float* __restrict__ w3, const float* __restrict__ b3){
    extern __shared__ float sm[];
    float* Hs  = sm;
    float* Ws  = Hs + 256*132;
    float* red = Ws + 128*132;
    float* f0s = red + 1024;
    float* f1s = f0s + 256;
    float* b2s = f1s + 256;
    float* w3s = b2s + 128;
    float* w1s = w3s + 128;
    float* b1s = w1s + 256;
    int tid = threadIdx.x;
    int pt0 = blockIdx.x*256;
    if(tid<256){
        int pt = pt0 + tid;
        int v = pt/TABN;
        int u = pt - v*TABN;
        f0s[tid] = -FMAXF + (float)u*TSTEP;
        f1s[tid] = -FMAXF + (float)v*TSTEP;
        w1s[tid] = w1[tid];
    }
    if(tid<128){ b1s[tid]=b1[tid]; b2s[tid]=b2[tid]; w3s[tid]=w3[tid]; }
    #pragma unroll
    for(int it=0; it<8; it++){
        int idx = tid + it*512;
        int k = idx>>5, n4 = (idx&31)*4;
        float4 v = *(const float4*)&w2[k*128 + n4];
        *(float4*)&Ws[k*132 + n4] = make_float4(tfr(v.x),tfr(v.y),tfr(v.z),tfr(v.w));
    }
    __syncthreads();
    #pragma unroll
    for(int it=0; it<16; it++){
        int idx = tid + it*512;
        int m = idx>>5, k4 = (idx&31)*4;
        float f0 = f0s[m], f1 = f1s[m];
        float4 wv0 = *(const float4*)&w1s[k4];
        float4 wv1 = *(const float4*)&w1s[128+k4];
        float4 bv  = *(const float4*)&b1s[k4];
        float4 h;
        h.x = tfr(fmaxf(f0*wv0.x + f1*wv1.x + bv.x, 0.f));
        h.y = tfr(fmaxf(f0*wv0.y + f1*wv1.y + bv.y, 0.f));
        h.z = tfr(fmaxf(f0*wv0.z + f1*wv1.z + bv.z, 0.f));
        h.w = tfr(fmaxf(f0*wv0.w + f1*wv1.w + bv.w, 0.f));
        *(float4*)&Hs[m*132 + k4] = h;
    }
    __syncthreads();

    int lane = tid&31, wid = tid>>5;
    int g = lane>>2, t = lane&3;
    int mbase = (wid&3)*64, nbase = (wid>>2)*32;
    float acc[4][4][4];
    #pragma unroll
    for(int a=0;a<4;a++){
        #pragma unroll
        for(int nn=0;nn<4;nn++){
            #pragma unroll
            for(int cc=0;cc<4;cc++) acc[a][nn][cc]=0.f; } }

    #pragma unroll 4
    for(int kc=0;kc<16;kc++){
        int K = kc*8;
        uint32_t af[4][4];
        #pragma unroll
        for(int mt=0;mt<4;mt++){
            const float* ap = Hs + (mbase+mt*16+g)*132 + K + t;
            af[mt][0] = __float_as_uint(ap[0]);
            af[mt][1] = __float_as_uint(ap[8*132]);
            af[mt][2] = __float_as_uint(ap[4]);
            af[mt][3] = __float_as_uint(ap[8*132+4]);
        }
        uint32_t bf[4][2];
        #pragma unroll
        for(int nt=0;nt<4;nt++){
            const float* bp = Ws + (K+t)*132 + nbase + nt*8 + g;
            bf[nt][0] = __float_as_uint(bp[0]);
            bf[nt][1] = __float_as_uint(bp[4*132]);
        }
        #pragma unroll
        for(int mt=0;mt<4;mt++){
            #pragma unroll
            for(int nt=0;nt<4;nt++) mma_tf32(acc[mt][nt], af[mt], bf[nt]);
        }
    }
    #pragma unroll
    for(int mt=0;mt<4;mt++){
        float pA=0.f, pB=0.f;
        #pragma unroll
        for(int nt=0;nt<4;nt++){
            int n = nbase + nt*8 + 2*t;
            float ba=b2s[n], bb=b2s[n+1], wa=w3s[n], wb=w3s[n+1];
            pA += fmaxf(acc[mt][nt][0]+ba,0.f)*wa + fmaxf(acc[mt][nt][1]+bb,0.f)*wb;
            pB += fmaxf(acc[mt][nt][2]+ba,0.f)*wa + fmaxf(acc[mt][nt][3]+bb,0.f)*wb;
        }
        pA += __shfl_xor_sync(0xffffffffu, pA, 1);
        pA += __shfl_xor_sync(0xffffffffu, pA, 2);
        pB += __shfl_xor_sync(0xffffffffu, pB, 1);
        pB += __shfl_xor_sync(0xffffffffu, pB, 2);
        if(t==0){
            int rA = mbase+mt*16+g;
            red[rA*4 + (wid>>2)]     = pA;
            red[(rA+8)*4 + (wid>>2)] = pB;
        }
    }
    __syncthreads();
    if(tid<256 && pt0+tid<TABN*TABN)
        g_tab[pt0+tid] = b3[0] + red[tid*4] + red[tid*4+1] + red[tid*4+2] + red[tid*4+3];
}

// ---------------- 5b) bias interpolation -> g_bias [bg][j][i] ----------------
__global__ void k_interp(){
    int idx = blockIdx.x*256 + threadIdx.x;
    int bg = idx>>16;
    int j  = (idx>>10)&63;
    int i  = idx&1023;
    float qx = 2.0f*(float)(i&31)*(1.0f/31.0f) - 1.0f;
    float qy = 2.0f*(float)(i>>5)*(1.0f/31.0f) - 1.0f;
    float2 kv = *(const float2*)&g_grid[(bg*JD+j)*2];
    float p0 = qx - kv.x, p1 = qy - kv.y;
    float f0 = copysignf(log1pf(fabsf(p0)), p0);
    float f1 = copysignf(log1pf(fabsf(p1)), p1);
    float u = fminf(fmaxf((f0+FMAXF)*TINV, 0.0f), 127.999f);
    float v = fminf(fmaxf((f1+FMAXF)*TINV, 0.0f), 127.999f);
    int iu=(int)u, iv=(int)v;
    float fu=u-(float)iu, fv=v-(float)iv;
    const float* t0 = g_tab + iv*TABN + iu;
    float a = t0[0]    + fu*(t0[1]-t0[0]);
    float b = t0[TABN] + fu*(t0[TABN+1]-t0[TABN]);
    g_bias[idx] = a + fv*(b-a);
}

// ---------------- 6) attention ----------------
__global__ void k_attn(){
    __shared__ float ks[DH*JD];
    __shared__ float vs[DH*JD];
    int bg=blockIdx.y, it=blockIdx.x, tid=threadIdx.x;
    int b=bg>>3, g=bg&7;
    for(int i=tid;i<DH*JD;i+=128){ ks[i]=g_k[bg*DH*JD+i]; vs[i]=g_v[bg*DH*JD+i]; }
    __syncthreads();
    int i = it*128 + tid;
    const float* qp = g_q + (b*NC+g*DH)*HW + i;
    float sim[JD];
    #pragma unroll
    for(int j=0;j<JD;j++) sim[j]=0.f;
    for(int d=0;d<DH;d++){
        float qv = qp[d*HW];
        #pragma unroll
        for(int j=0;j<JD;j++) sim[j] += qv*ks[d*JD+j];
    }
    const float scale = 0.125f;
    const float* bp = g_bias + bg*JD*HW + i;
    float m=-1e30f;
    #pragma unroll
    for(int j=0;j<JD;j++){ sim[j] = sim[j]*scale + bp[j*HW]; m=fmaxf(m,sim[j]); }
    float ssum=0.f;
    #pragma unroll
    for(int j=0;j<JD;j++){ sim[j]=expf(sim[j]-m); ssum+=sim[j]; }
    float inv = 1.0f/ssum;
    float* op = g_attn + (b*NC+g*DH)*HW + i;
    for(int d=0;d<DH;d++){
        float a=0.f;
        #pragma unroll
        for(int j=0;j<JD;j++) a += sim[j]*vs[d*JD+j];
        op[d*HW] = a*inv;
    }
}

// ---------------- cp.async double-buffered tf32 GEMM core (no cvt: HW truncates) ----------------
template<int MT, int KTOT>
__device__ __forceinline__ void gemm_core(const float* __restrict__ A,
                                          const float* __restrict__ Bb,
                                          int m0, int p0,
                                          float* As, float* Bs,
                                          float (*acc)[4][4]){
    constexpr int BM = MT*32;
    constexpr int NA = BM/32;        // A float4 chunks per thread per stage
    constexpr int NS = KTOT/32;
    int tid=threadIdx.x, lane=tid&31, wid=tid>>5;
    int g=lane>>2, t=lane&3;
    int mbase=(wid&1)*MT*16, nbase=(wid>>1)*32;

    auto prefetch = [&](int s, int buf){
        int k0 = s*32;
        float* Ad = As + buf*BM*36;
        float* Bd = Bs + buf*32*132;
        #pragma unroll
        for(int ia=0; ia<NA; ia++){
            int idx = tid + ia*256;
            cpa16(Ad + (idx>>3)*36 + (idx&7)*4, A + (m0+(idx>>3))*KTOT + k0 + (idx&7)*4);
        }
        #pragma unroll
        for(int ib=0; ib<4; ib++){
            int idx = tid + ib*256;
            cpa16(Bd + (idx>>5)*132 + (idx&31)*4, Bb + (k0+(idx>>5))*HW + p0 + (idx&31)*4);
        }
        asm volatile("cp.async.commit_group;");
    };

    prefetch(0,0);
    for(int s=0; s<NS; s++){
        if(s+1<NS){
            prefetch(s+1,(s+1)&1);
            asm volatile("cp.async.wait_group 1;");
        } else {
            asm volatile("cp.async.wait_group 0;");
        }
        __syncthreads();
        const float* Ac = As + (s&1)*BM*36;
        const float* Bc = Bs + (s&1)*32*132;
        #pragma unroll
        for(int kc=0;kc<4;kc++){
            int K = kc*8;
            uint32_t af[MT][4];
            #pragma unroll
            for(int mt=0;mt<MT;mt++){
                const float* ap = Ac + (mbase+mt*16+g)*36 + K + t;
                af[mt][0] = __float_as_uint(ap[0]);
                af[mt][1] = __float_as_uint(ap[8*36]);
                af[mt][2] = __float_as_uint(ap[4]);
                af[mt][3] = __float_as_uint(ap[8*36+4]);
            }
            uint32_t bf[4][2];
            #pragma unroll
            for(int nt=0;nt<4;nt++){
                const float* bp = Bc + (K+t)*132 + nbase + nt*8 + g;
                bf[nt][0] = __float_as_uint(bp[0]);
                bf[nt][1] = __float_as_uint(bp[4*132]);
            }
            #pragma unroll
            for(int mt=0;mt<MT;mt++){
                #pragma unroll
                for(int nt=0;nt<4;nt++) mma_tf32(acc[mt][nt], af[mt], bf[nt]);
            }
        }
        __syncthreads();
    }
}

// ---------------- 7) out projection + residual + fused bn2 ----------------
__global__ void __launch_bounds__(256,2) k_outproj(
        const float* __restrict__ ow, const float* __restrict__ ob,
        const float* __restrict__ x, const float* __restrict__ g2,
        const float* __restrict__ bb2){
    extern __shared__ float smp[];
    float* As = smp;                    // 2*64*36
    float* Bs = smp + 2*64*36;          // 2*32*132
    int m0 = blockIdx.y*64, n0 = blockIdx.x*128;
    int b = n0>>10, p0 = n0&1023;
    float acc[2][4][4];
    #pragma unroll
    for(int a=0;a<2;a++){ 
        #pragma unroll
        for(int nn=0;nn<4;nn++){ 
            #pragma unroll
            for(int cc=0;cc<4;cc++) acc[a][nn][cc]=0.f; } }
    gemm_core<2,512>(ow, g_attn + b*NC*HW, m0, p0, As, Bs, acc);
    int tid=threadIdx.x, lane=tid&31, wid=tid>>5;
    int g=lane>>2, t=lane&3;
    int mbase=(wid&1)*32, nbase=(wid>>1)*32;
    #pragma unroll
    for(int mt=0;mt<2;mt++){
        int mr = m0 + mbase + mt*16 + g;
        float bi0=ob[mr], bi1=ob[mr+8];
        float s0=g2[mr]*rsqrtf(1.0f+EPSBN), s1=g2[mr+8]*rsqrtf(1.0f+EPSBN);
        float c0=bb2[mr], c1=bb2[mr+8];
        #pragma unroll
        for(int nt=0;nt<4;nt++){
            int n = p0 + nbase + nt*8 + 2*t;
            int off0 = (b*NC + mr)*HW + n;
            int off1 = (b*NC + mr+8)*HW + n;
            float2 xv0 = *(const float2*)&x[off0];
            float2 xv1 = *(const float2*)&x[off1];
            float2 v0 = { xv0.x + acc[mt][nt][0] + bi0, xv0.y + acc[mt][nt][1] + bi0 };
            float2 v1 = { xv1.x + acc[mt][nt][2] + bi1, xv1.y + acc[mt][nt][3] + bi1 };
            *(float2*)&g_x2[off0] = v0;
            *(float2*)&g_x2[off1] = v1;
            float2 n0v = { v0.x*s0+c0, v0.y*s0+c0 };
            float2 n1v = { v1.x*s1+c1, v1.y*s1+c1 };
            *(float2*)&g_xn2[off0] = n0v;
            *(float2*)&g_xn2[off1] = n1v;
        }
    }
}

// ---------------- 8) MLP conv1 ----------------
__global__ void __launch_bounds__(256,2) k_mlp1(
        const float* __restrict__ w, const float* __restrict__ bias){
    extern __shared__ float smp[];
    float* As = smp;                    // 2*128*36
    float* Bs = smp + 2*128*36;         // 2*32*132
    int m0 = blockIdx.y*128, n0 = blockIdx.x*128;
    int b = n0>>10, p0 = n0&1023;
    float acc[4][4][4];
    #pragma unroll
    for(int a=0;a<4;a++){ 
        #pragma unroll
        for(int nn=0;nn<4;nn++){ 
            #pragma unroll
            for(int cc=0;cc<4;cc++) acc[a][nn][cc]=0.f; } }
    gemm_core<4,512>(w, g_xn2 + b*NC*HW, m0, p0, As, Bs, acc);
    int tid=threadIdx.x, lane=tid&31, wid=tid>>5;
    int g=lane>>2, t=lane&3;
    int mbase=(wid&1)*64, nbase=(wid>>1)*32;
    #pragma unroll
    for(int mt=0;mt<4;mt++){
        int mr = m0 + mbase + mt*16 + g;
        float bi0=bias[mr], bi1=bias[mr+8];
        #pragma unroll
        for(int nt=0;nt<4;nt++){
            int n = p0 + nbase + nt*8 + 2*t;
            float2 v0 = { gelu_exact(acc[mt][nt][0]+bi0), gelu_exact(acc[mt][nt][1]+bi0) };
            float2 v1 = { gelu_exact(acc[mt][nt][2]+bi1), gelu_exact(acc[mt][nt][3]+bi1) };
            *(float2*)&g_h1[(b*2048 + mr)*HW + n]   = v0;
            *(float2*)&g_h1[(b*2048 + mr+8)*HW + n] = v1;
        }
    }
}

// ---------------- 9) MLP conv2 + residual ----------------
__global__ void __launch_bounds__(256,2) k_mlp2(
        const float* __restrict__ w, const float* __restrict__ bias,
        float* __restrict__ out){
    extern __shared__ float smp[];
    float* As = smp;                    // 2*64*36
    float* Bs = smp + 2*64*36;          // 2*32*132
    int m0 = blockIdx.y*64, n0 = blockIdx.x*128;
    int b = n0>>10, p0 = n0&1023;
    float acc[2][4][4];
    #pragma unroll
    for(int a=0;a<2;a++){ 
        #pragma unroll
        for(int nn=0;nn<4;nn++){ 
            #pragma unroll
            for(int cc=0;cc<4;cc++) acc[a][nn][cc]=0.f; } }
    gemm_core<2,2048>(w, g_h1 + b*2048*HW, m0, p0, As, Bs, acc);
    int tid=threadIdx.x, lane=tid&31, wid=tid>>5;
    int g=lane>>2, t=lane&3;
    int mbase=(wid&1)*32, nbase=(wid>>1)*32;
    #pragma unroll
    for(int mt=0;mt<2;mt++){
        int mr = m0 + mbase + mt*16 + g;
        float bi0=bias[mr], bi1=bias[mr+8];
        #pragma unroll
        for(int nt=0;nt<4;nt++){
            int n = p0 + nbase + nt*8 + 2*t;
            int off0 = (b*NC + mr)*HW + n;
            int off1 = (b*NC + mr+8)*HW + n;
            float2 r0 = *(const float2*)&g_x2[off0];
            float2 r1 = *(const float2*)&g_x2[off1];
            float2 v0 = { r0.x + acc[mt][nt][0] + bi0, r0.y + acc[mt][nt][1] + bi0 };
            float2 v1 = { r1.x + acc[mt][nt][2] + bi1, r1.y + acc[mt][nt][3] + bi1 };
            *(float2*)&out[off0] = v0;
            *(float2*)&out[off1] = v1;
        }
    }
}

// ---------------- launch ----------------
extern "C" void kernel_launch(void* const* d_in, const int* in_sizes, int n_in,
                              void* d_out, int out_size){
    const float* x    = (const float*)d_in[0];
    const float* bn1g = (const float*)d_in[1];
    const float* bn1b = (const float*)d_in[2];
    const float* bn2g = (const float*)d_in[3];
    const float* bn2b = (const float*)d_in[4];
    const float* qw   = (const float*)d_in[5];
    const float* kw   = (const float*)d_in[6];
    const float* vw   = (const float*)d_in[7];
    const float* ow   = (const float*)d_in[8];
    const float* obv  = (const float*)d_in[9];
    const float* dw   = (const float*)d_in[10];
    const float* dwb  = (const float*)d_in[11];
    const float* pw   = (const float*)d_in[12];
    const float* cw1  = (const float*)d_in[13];
    const float* cb1  = (const float*)d_in[14];
    const float* cw2  = (const float*)d_in[15];
    const float* cb2  = (const float*)d_in[16];
    const float* cw3  = (const float*)d_in[17];
    const float* cb3  = (const float*)d_in[18];
    const float* mw1  = (const float*)d_in[19];
    const float* mb1  = (const float*)d_in[20];
    const float* mw2  = (const float*)d_in[21];
    const float* mb2  = (const float*)d_in[22];
    float* out = (float*)d_out;

    const int tab_smem  = (256*132 + 128*132 + 1024 + 512 + 256 + 256 + 128) * 4;
    const int gem2_smem = (2*64*36 + 2*32*132) * 4;    // 52224
    const int gem4_smem = (2*128*36 + 2*32*132) * 4;   // 70656

    static bool init = false;
    static cudaStream_t s1;
    static cudaEvent_t evF, evOff, evInt;
    if(!init){
        cudaStreamCreateWithFlags(&s1, cudaStreamNonBlocking);
        cudaEventCreateWithFlags(&evF,   cudaEventDisableTiming);
        cudaEventCreateWithFlags(&evOff, cudaEventDisableTiming);
        cudaEventCreateWithFlags(&evInt, cudaEventDisableTiming);
        cudaFuncSetAttribute(k_tab,     cudaFuncAttributeMaxDynamicSharedMemorySize, tab_smem);
        cudaFuncSetAttribute(k_outproj, cudaFuncAttributeMaxDynamicSharedMemorySize, gem2_smem);
        cudaFuncSetAttribute(k_mlp1,    cudaFuncAttributeMaxDynamicSharedMemorySize, gem4_smem);
        cudaFuncSetAttribute(k_mlp2,    cudaFuncAttributeMaxDynamicSharedMemorySize, gem2_smem);
        init = true;
    }

    // fork: k_tab depends only on weights -> side stream
    cudaEventRecord(evF, 0);
    cudaStreamWaitEvent(s1, evF, 0);
    k_tab<<<66,512,tab_smem,s1>>>(cw1,cb1,cw2,cb2,cw3,cb3);

    k_bn1    <<<1024,256>>>(x,bn1g,bn1b);
    k_qproj  <<<dim3(8,16),128>>>(qw);
    k_offsets<<<128,256>>>(dw,dwb,pw);
    cudaEventRecord(evOff, 0);

    k_sample <<<dim3(16,4),256>>>(kw,vw);

    // interp on side stream, parallel with k_sample (needs tab + offsets)
    cudaStreamWaitEvent(s1, evOff, 0);
    k_interp <<<4096,256,0,s1>>>();
    cudaEventRecord(evInt, s1);

    cudaStreamWaitEvent(0, evInt, 0);
    k_attn   <<<dim3(8,16),128>>>();
    k_outproj<<<dim3(16,8),256,gem2_smem>>>(ow,obv,x,bn2g,bn2b);
    k_mlp1   <<<dim3(16,16),256,gem4_smem>>>(mw1,mb1);
    k_mlp2   <<<dim3(16,8),256,gem2_smem>>>(mw2,mb2,out);
}